// round 3
// baseline (speedup 1.0000x reference)
#include <cuda_runtime.h>
#include <math.h>

#define SQ    4096
#define NH_   16
#define NKV_  2
#define HD_   128
#define HID_  2048
#define GRP_  8

// ---------------- scratch (device globals; no allocation allowed) ----------------
__device__ float g_q[SQ * NH_ * HD_];      // [s][h*128+d]
__device__ float g_k[SQ * NKV_ * HD_];     // [s][kv*128+d]
__device__ float g_v[SQ * NKV_ * HD_];
__device__ float g_attn[SQ * NH_ * HD_];   // attention out, pre O-proj
__device__ float g_m[NH_ * SQ];            // row max of scaled logits
__device__ float g_l[NH_ * SQ];            // row sum-exp
__device__ float g_colsum[NH_ * SQ];       // per-head column sums of probs

// ---------------- generic NT GEMM: C[M,N] = A[M,K] * B[N,K]^T (+bias) ----------------
// BM=BN=128, BK=8, 256 threads, 8x8 per thread
__global__ __launch_bounds__(256)
void gemm_nt(const float* __restrict__ A, const float* __restrict__ B,
             const float* __restrict__ bias, float* __restrict__ C,
             int M, int N, int K)
{
    __shared__ float As[8][128];
    __shared__ float Bs[8][128];
    const int tid  = threadIdx.x;
    const int row0 = blockIdx.y * 128;
    const int col0 = blockIdx.x * 128;
    const int tx = tid & 15, ty = tid >> 4;
    const int lr = tid >> 1;
    const int lc = (tid & 1) * 4;
    const float* Ag = A + (size_t)(row0 + lr) * K + lc;
    const float* Bg = B + (size_t)(col0 + lr) * K + lc;

    float acc[8][8];
#pragma unroll
    for (int i = 0; i < 8; i++)
#pragma unroll
        for (int j = 0; j < 8; j++) acc[i][j] = 0.f;

    for (int k0 = 0; k0 < K; k0 += 8) {
        float4 a4 = *(const float4*)(Ag + k0);
        float4 b4 = *(const float4*)(Bg + k0);
        As[lc+0][lr] = a4.x; As[lc+1][lr] = a4.y; As[lc+2][lr] = a4.z; As[lc+3][lr] = a4.w;
        Bs[lc+0][lr] = b4.x; Bs[lc+1][lr] = b4.y; Bs[lc+2][lr] = b4.z; Bs[lc+3][lr] = b4.w;
        __syncthreads();
#pragma unroll
        for (int kk = 0; kk < 8; kk++) {
            float4 a0 = *(const float4*)&As[kk][ty*8];
            float4 a1 = *(const float4*)&As[kk][ty*8+4];
            float4 b0 = *(const float4*)&Bs[kk][tx*8];
            float4 b1 = *(const float4*)&Bs[kk][tx*8+4];
            float a[8] = {a0.x,a0.y,a0.z,a0.w,a1.x,a1.y,a1.z,a1.w};
            float b[8] = {b0.x,b0.y,b0.z,b0.w,b1.x,b1.y,b1.z,b1.w};
#pragma unroll
            for (int i = 0; i < 8; i++)
#pragma unroll
                for (int j = 0; j < 8; j++)
                    acc[i][j] += a[i] * b[j];
        }
        __syncthreads();
    }
#pragma unroll
    for (int i = 0; i < 8; i++) {
        int r = row0 + ty*8 + i;
#pragma unroll
        for (int j = 0; j < 8; j++) {
            int c = col0 + tx*8 + j;
            float v = acc[i][j];
            if (bias) v += bias[c];
            C[(size_t)r * N + c] = v;
        }
    }
}

// ---------------- RoPE in-place: x layout [s][h*128 + d] ----------------
__global__ void rope_kernel(float* __restrict__ x, int nheads, int total)
{
    int idx = blockIdx.x * blockDim.x + threadIdx.x;
    if (idx >= total) return;
    int j = idx & 63;
    int h = (idx >> 6) % nheads;
    int s = (idx >> 6) / nheads;
    float inv = (float)pow(1.0e6, -(double)j / 64.0);
    float fr  = (float)s * inv;
    float c, sn;
    sincosf(fr, &sn, &c);
    float* p = x + (size_t)s * nheads * HD_ + h * HD_;
    float x1 = p[j], x2 = p[j + 64];
    p[j]      = x1 * c - x2 * sn;
    p[j + 64] = x2 * c + x1 * sn;
}

// ---------------- attention pass 1: per-row max + sum-exp ----------------
// grid (32, 16): 128 q rows per block (reversed so heavy blocks start first), one head.
__global__ __launch_bounds__(256)
void attn_pass1()
{
    const int qb   = gridDim.x - 1 - blockIdx.x;
    const int h    = blockIdx.y;
    const int kv   = h >> 3;
    const int row0 = qb * 128;
    const int tid  = threadIdx.x;
    const int tx = tid & 15, ty = tid >> 4;
    __shared__ float Qs[16][128];
    __shared__ float Ks[16][64];
    const float scale = 0.08838834764831845f;  // 1/sqrt(128)

    float m_run[8], l_run[8];
#pragma unroll
    for (int i = 0; i < 8; i++) { m_run[i] = -1e30f; l_run[i] = 0.f; }

    const int nj = 2 * qb + 2;
    for (int jb = 0; jb < nj; jb++) {
        const int col0 = jb * 64;
        float acc[8][4];
#pragma unroll
        for (int i = 0; i < 8; i++)
#pragma unroll
            for (int j = 0; j < 4; j++) acc[i][j] = 0.f;

        for (int d0 = 0; d0 < HD_; d0 += 16) {
#pragma unroll
            for (int q = 0; q < 2; q++) {
                int fid = tid * 2 + q;       // 0..511 float4s, Q tile 128x16
                int r = fid >> 2;
                int c = (fid & 3) * 4;
                float4 v = *(const float4*)&g_q[(size_t)(row0 + r) * (NH_*HD_) + h*HD_ + d0 + c];
                Qs[c+0][r] = v.x; Qs[c+1][r] = v.y; Qs[c+2][r] = v.z; Qs[c+3][r] = v.w;
            }
            {
                int r = tid >> 2;            // K tile 64x16
                int c = (tid & 3) * 4;
                float4 v = *(const float4*)&g_k[(size_t)(col0 + r) * (NKV_*HD_) + kv*HD_ + d0 + c];
                Ks[c+0][r] = v.x; Ks[c+1][r] = v.y; Ks[c+2][r] = v.z; Ks[c+3][r] = v.w;
            }
            __syncthreads();
#pragma unroll
            for (int kk = 0; kk < 16; kk++) {
                float4 a0 = *(const float4*)&Qs[kk][ty*8];
                float4 a1 = *(const float4*)&Qs[kk][ty*8+4];
                float4 b0 = *(const float4*)&Ks[kk][tx*4];
                float a[8] = {a0.x,a0.y,a0.z,a0.w,a1.x,a1.y,a1.z,a1.w};
                float b[4] = {b0.x,b0.y,b0.z,b0.w};
#pragma unroll
                for (int i = 0; i < 8; i++)
#pragma unroll
                    for (int j = 0; j < 4; j++)
                        acc[i][j] += a[i] * b[j];
            }
            __syncthreads();
        }
        // scale + causal mask + online (m, l) update; rows reduced across tx (16 lanes)
#pragma unroll
        for (int i = 0; i < 8; i++) {
            int qi = row0 + ty*8 + i;
            float s0 = (col0 + tx*4 + 0 <= qi) ? acc[i][0]*scale : -1e30f;
            float s1 = (col0 + tx*4 + 1 <= qi) ? acc[i][1]*scale : -1e30f;
            float s2 = (col0 + tx*4 + 2 <= qi) ? acc[i][2]*scale : -1e30f;
            float s3 = (col0 + tx*4 + 3 <= qi) ? acc[i][3]*scale : -1e30f;
            float rmax = fmaxf(fmaxf(s0, s1), fmaxf(s2, s3));
#pragma unroll
            for (int o = 8; o; o >>= 1) rmax = fmaxf(rmax, __shfl_xor_sync(0xffffffffu, rmax, o));
            float nm = fmaxf(m_run[i], rmax);
            float ssum = expf(s0 - nm) + expf(s1 - nm) + expf(s2 - nm) + expf(s3 - nm);
#pragma unroll
            for (int o = 8; o; o >>= 1) ssum += __shfl_xor_sync(0xffffffffu, ssum, o);
            l_run[i] = l_run[i] * expf(m_run[i] - nm) + ssum;
            m_run[i] = nm;
        }
    }
    if (tx == 0) {
#pragma unroll
        for (int i = 0; i < 8; i++) {
            int qi = row0 + ty*8 + i;
            g_m[h*SQ + qi] = m_run[i];
            g_l[h*SQ + qi] = l_run[i];
        }
    }
}

// ---------------- zero colsum ----------------
__global__ void zero_colsum()
{
    int i = blockIdx.x * blockDim.x + threadIdx.x;
    g_colsum[i] = 0.f;
}

// ---------------- attention pass 2: exact probs -> O and column sums ----------------
#define P2_SMEM_FLOATS (64*128 + 128*68 + 16*128 + 16*64)
__global__ __launch_bounds__(256)
void attn_pass2()
{
    const int qb   = gridDim.x - 1 - blockIdx.x;
    const int h    = blockIdx.y;
    const int kv   = h >> 3;
    const int row0 = qb * 128;
    const int tid  = threadIdx.x;
    const int tx = tid & 15, ty = tid >> 4;
    extern __shared__ float sm[];
    float* Vs = sm;                 // [64][128]
    float* Ps = Vs + 64*128;        // [128][68] (padded stride 68)
    float* Qs = Ps + 128*68;        // [16][128]
    float* Ks = Qs + 16*128;        // [16][64]
    const float scale = 0.08838834764831845f;

    float o_acc[8][8];
#pragma unroll
    for (int i = 0; i < 8; i++)
#pragma unroll
        for (int j = 0; j < 8; j++) o_acc[i][j] = 0.f;

    float mr[8], il[8];
#pragma unroll
    for (int i = 0; i < 8; i++) {
        int qi = row0 + ty*8 + i;
        mr[i] = g_m[h*SQ + qi];
        il[i] = 1.0f / g_l[h*SQ + qi];
    }

    const int nj = 2 * qb + 2;
    for (int jb = 0; jb < nj; jb++) {
        const int col0 = jb * 64;
        // stage V tile [64][128]
#pragma unroll
        for (int q = 0; q < 8; q++) {
            int fid = tid + q * 256;     // 0..2047 float4s
            int r = fid >> 5;
            int c = (fid & 31) * 4;
            float4 v = *(const float4*)&g_v[(size_t)(col0 + r) * (NKV_*HD_) + kv*HD_ + c];
            *(float4*)&Vs[r*128 + c] = v;
        }
        // S = Q K^T (d-chunked)
        float acc[8][4];
#pragma unroll
        for (int i = 0; i < 8; i++)
#pragma unroll
            for (int j = 0; j < 4; j++) acc[i][j] = 0.f;

        for (int d0 = 0; d0 < HD_; d0 += 16) {
#pragma unroll
            for (int q = 0; q < 2; q++) {
                int fid = tid * 2 + q;
                int r = fid >> 2;
                int c = (fid & 3) * 4;
                float4 v = *(const float4*)&g_q[(size_t)(row0 + r) * (NH_*HD_) + h*HD_ + d0 + c];
                Qs[(c+0)*128 + r] = v.x; Qs[(c+1)*128 + r] = v.y;
                Qs[(c+2)*128 + r] = v.z; Qs[(c+3)*128 + r] = v.w;
            }
            {
                int r = tid >> 2;
                int c = (tid & 3) * 4;
                float4 v = *(const float4*)&g_k[(size_t)(col0 + r) * (NKV_*HD_) + kv*HD_ + d0 + c];
                Ks[(c+0)*64 + r] = v.x; Ks[(c+1)*64 + r] = v.y;
                Ks[(c+2)*64 + r] = v.z; Ks[(c+3)*64 + r] = v.w;
            }
            __syncthreads();
#pragma unroll
            for (int kk = 0; kk < 16; kk++) {
                float4 a0 = *(const float4*)&Qs[kk*128 + ty*8];
                float4 a1 = *(const float4*)&Qs[kk*128 + ty*8 + 4];
                float4 b0 = *(const float4*)&Ks[kk*64 + tx*4];
                float a[8] = {a0.x,a0.y,a0.z,a0.w,a1.x,a1.y,a1.z,a1.w};
                float b[4] = {b0.x,b0.y,b0.z,b0.w};
#pragma unroll
                for (int i = 0; i < 8; i++)
#pragma unroll
                    for (int j = 0; j < 4; j++)
                        acc[i][j] += a[i] * b[j];
            }
            __syncthreads();
        }
        // exact probs into Ps
#pragma unroll
        for (int i = 0; i < 8; i++) {
            int qi = row0 + ty*8 + i;
#pragma unroll
            for (int j = 0; j < 4; j++) {
                int kj = col0 + tx*4 + j;
                float sv = (kj <= qi) ? acc[i][j]*scale : -1e30f;
                float p  = expf(sv - mr[i]) * il[i];
                Ps[(ty*8 + i)*68 + tx*4 + j] = p;
            }
        }
        __syncthreads();
        // column sums for accumulated_scores
        if (tid < 64) {
            float cs = 0.f;
#pragma unroll 8
            for (int r = 0; r < 128; r++) cs += Ps[r*68 + tid];
            atomicAdd(&g_colsum[h*SQ + col0 + tid], cs);
        }
        // O += P @ V
#pragma unroll 4
        for (int kk = 0; kk < 64; kk++) {
            float4 v0 = *(const float4*)&Vs[kk*128 + tx*8];
            float4 v1 = *(const float4*)&Vs[kk*128 + tx*8 + 4];
            float b[8] = {v0.x,v0.y,v0.z,v0.w,v1.x,v1.y,v1.z,v1.w};
#pragma unroll
            for (int i = 0; i < 8; i++) {
                float pv = Ps[(ty*8 + i)*68 + kk];
#pragma unroll
                for (int j = 0; j < 8; j++)
                    o_acc[i][j] += pv * b[j];
            }
        }
        __syncthreads();
    }
#pragma unroll
    for (int i = 0; i < 8; i++) {
        int r = row0 + ty*8 + i;
#pragma unroll
        for (int j = 0; j < 8; j++)
            g_attn[(size_t)r * (NH_*HD_) + h*HD_ + tx*8 + j] = o_acc[i][j];
    }
}

// ---------------- finalize accumulated_scores: mean over group, both kv heads ----------------
__global__ void finalize_acc(float* __restrict__ out_acc)
{
    int idx = blockIdx.x * blockDim.x + threadIdx.x;  // 0..8191
    int kvh = idx >> 12;
    int col = idx & 4095;
    float s = 0.f;
#pragma unroll
    for (int g = 0; g < GRP_; g++)
        s += g_colsum[(kvh*GRP_ + g)*SQ + col];
    out_acc[idx] = s * 0.125f;
}

// ---------------- launch ----------------
extern "C" void kernel_launch(void* const* d_in, const int* in_sizes, int n_in,
                              void* d_out, int out_size)
{
    const float* hs = (const float*)d_in[0];
    const float* qw = (const float*)d_in[1];
    const float* qb = (const float*)d_in[2];
    const float* kw = (const float*)d_in[3];
    const float* kb = (const float*)d_in[4];
    const float* vw = (const float*)d_in[5];
    const float* vb = (const float*)d_in[6];
    const float* ow = (const float*)d_in[7];
    float* out = (float*)d_out;

    float *qp, *kp, *vp, *ap;
    cudaGetSymbolAddress((void**)&qp, g_q);
    cudaGetSymbolAddress((void**)&kp, g_k);
    cudaGetSymbolAddress((void**)&vp, g_v);
    cudaGetSymbolAddress((void**)&ap, g_attn);

    cudaFuncSetAttribute(attn_pass2, cudaFuncAttributeMaxDynamicSharedMemorySize,
                         P2_SMEM_FLOATS * (int)sizeof(float));

    // projections (+bias)
    gemm_nt<<<dim3(16, 32), 256>>>(hs, qw, qb, qp, SQ, NH_*HD_, HID_);
    gemm_nt<<<dim3(2,  32), 256>>>(hs, kw, kb, kp, SQ, NKV_*HD_, HID_);
    gemm_nt<<<dim3(2,  32), 256>>>(hs, vw, vb, vp, SQ, NKV_*HD_, HID_);
    // rope
    rope_kernel<<<(SQ*NH_*64)/256,  256>>>(qp, NH_,  SQ*NH_*64);
    rope_kernel<<<(SQ*NKV_*64)/256, 256>>>(kp, NKV_, SQ*NKV_*64);
    // attention
    attn_pass1<<<dim3(32, 16), 256>>>();
    zero_colsum<<<(NH_*SQ)/256, 256>>>();
    attn_pass2<<<dim3(32, 16), 256, P2_SMEM_FLOATS * (int)sizeof(float)>>>();
    // output projection -> first part of d_out
    gemm_nt<<<dim3(16, 32), 256>>>(ap, ow, nullptr, out, SQ, HID_, NH_*HD_);
    // accumulated_scores -> tail of d_out
    finalize_acc<<<(NKV_*SQ)/256, 256>>>(out + (out_size - NKV_*SQ));
}

// round 5
// speedup vs baseline: 1.5386x; 1.5386x over previous
#include <cuda_runtime.h>
#include <mma.h>
#include <math.h>

using namespace nvcuda;

#define SQ    4096
#define NH_   16
#define NKV_  2
#define HD_   128
#define HID_  2048
#define GRP_  8

// ---------------- scratch (device globals; no allocation allowed) ----------------
__device__ float g_q[SQ * NH_ * HD_];      // [s][h*128+d]
__device__ float g_k[SQ * NKV_ * HD_];     // [s][kv*128+d]
__device__ float g_v[SQ * NKV_ * HD_];
__device__ float g_attn[SQ * NH_ * HD_];   // attention out, pre O-proj
__device__ float g_m[NH_ * SQ];            // row max of scaled logits
__device__ float g_l[NH_ * SQ];            // row sum-exp
__device__ float g_colsum[NH_ * SQ];       // per-head column sums of probs
__device__ float g_invfreq[64];

__device__ __forceinline__ float t32(float x) { return wmma::__float_to_tf32(x); }

// ---------------- exact inv_freq table (fp64 once, 64 threads) ----------------
__global__ void compute_invfreq()
{
    int j = threadIdx.x;
    if (j < 64) g_invfreq[j] = (float)(1.0 / pow(1.0e6, (double)j / 64.0));
}

// ---------------- TF32 NT GEMM: C[M,N] = A[M,K] * B[N,K]^T ----------------
// BM=BN=128, BK=32, 256 threads (8 warps), warp tile 64x32 (4x2 of 16x16x8)
__global__ __launch_bounds__(256)
void gemm_nt_tf32(const float* __restrict__ A, const float* __restrict__ B,
                  float* __restrict__ C, int M, int N, int K)
{
    __shared__ float As[128 * 36];   // [m][k] ld=36
    __shared__ float Bs[128 * 36];   // [n][k] ld=36
    const int tid  = threadIdx.x;
    const int warp = tid >> 5;
    const int wm = warp >> 2;        // 0..1 -> 64 rows
    const int wn = warp & 3;         // 0..3 -> 32 cols
    const int row0 = blockIdx.y * 128;
    const int col0 = blockIdx.x * 128;

    wmma::fragment<wmma::accumulator, 16, 16, 8, float> acc[4][2];
#pragma unroll
    for (int i = 0; i < 4; i++)
#pragma unroll
        for (int j = 0; j < 2; j++) wmma::fill_fragment(acc[i][j], 0.0f);

    for (int k0 = 0; k0 < K; k0 += 32) {
#pragma unroll
        for (int it = 0; it < 4; it++) {
            int fid = tid + it * 256;       // 1024 float4 per tile
            int r = fid >> 3;
            int c = (fid & 7) * 4;
            float4 a = *(const float4*)&A[(size_t)(row0 + r) * K + k0 + c];
            As[r*36+c+0] = t32(a.x); As[r*36+c+1] = t32(a.y);
            As[r*36+c+2] = t32(a.z); As[r*36+c+3] = t32(a.w);
            float4 b = *(const float4*)&B[(size_t)(col0 + r) * K + k0 + c];
            Bs[r*36+c+0] = t32(b.x); Bs[r*36+c+1] = t32(b.y);
            Bs[r*36+c+2] = t32(b.z); Bs[r*36+c+3] = t32(b.w);
        }
        __syncthreads();
#pragma unroll
        for (int kk = 0; kk < 32; kk += 8) {
            wmma::fragment<wmma::matrix_a, 16, 16, 8, wmma::precision::tf32, wmma::row_major> af[4];
            wmma::fragment<wmma::matrix_b, 16, 16, 8, wmma::precision::tf32, wmma::col_major> bf[2];
#pragma unroll
            for (int i = 0; i < 4; i++)
                wmma::load_matrix_sync(af[i], &As[(wm*64 + i*16)*36 + kk], 36);
#pragma unroll
            for (int j = 0; j < 2; j++)
                wmma::load_matrix_sync(bf[j], &Bs[(wn*32 + j*16)*36 + kk], 36);
#pragma unroll
            for (int i = 0; i < 4; i++)
#pragma unroll
                for (int j = 0; j < 2; j++)
                    wmma::mma_sync(acc[i][j], af[i], bf[j], acc[i][j]);
        }
        __syncthreads();
    }
#pragma unroll
    for (int i = 0; i < 4; i++)
#pragma unroll
        for (int j = 0; j < 2; j++)
            wmma::store_matrix_sync(&C[(size_t)(row0 + wm*64 + i*16) * N + col0 + wn*32 + j*16],
                                    acc[i][j], N, wmma::mem_row_major);
}

// ---------------- RoPE in-place with fused bias add ----------------
__global__ void rope_bias_kernel(float* __restrict__ x, const float* __restrict__ bias,
                                 int nheads, int total)
{
    int idx = blockIdx.x * blockDim.x + threadIdx.x;
    if (idx >= total) return;
    int j = idx & 63;
    int h = (idx >> 6) % nheads;
    int s = (idx >> 6) / nheads;
    float fr = (float)s * g_invfreq[j];
    float c, sn;
    sincosf(fr, &sn, &c);
    float* p = x + (size_t)s * nheads * HD_ + h * HD_;
    float x1 = p[j]      + bias[h*HD_ + j];
    float x2 = p[j + 64] + bias[h*HD_ + j + 64];
    p[j]      = x1 * c - x2 * sn;
    p[j + 64] = x2 * c + x1 * sn;
}

// ---------------- V bias add ----------------
__global__ void bias_v_kernel(float* __restrict__ v, const float* __restrict__ b)
{
    int i = blockIdx.x * blockDim.x + threadIdx.x;
    v[i] += b[i & (NKV_*HD_ - 1)];
}

// ---------------- attention pass 1: per-row max + sum-exp (TF32 wmma S) ----------------
#define P1_SMEM ((128*132 + 64*132 + 128*72) * 4)
__global__ __launch_bounds__(256)
void attn_pass1_t()
{
    extern __shared__ float sm[];
    float* Qs = sm;                  // [128][132]
    float* Ks = Qs + 128*132;        // [64][132]
    float* Ss = Ks + 64*132;         // [128][72]
    const int qb   = gridDim.x - 1 - blockIdx.x;
    const int h    = blockIdx.y;
    const int kv   = h >> 3;
    const int row0 = qb * 128;
    const int tid  = threadIdx.x;
    const int warp = tid >> 5;
    const int wm = warp >> 1;        // 0..3 -> 32 rows
    const int wn = warp & 1;         // 0..1 -> 32 cols
    const float scale = 0.08838834764831845f;

    // stage Q once (tf32-rounded)
#pragma unroll
    for (int it = 0; it < 16; it++) {
        int fid = tid + it * 256;
        int r = fid >> 5, c = (fid & 31) * 4;
        float4 v = *(const float4*)&g_q[(size_t)(row0 + r) * (NH_*HD_) + h*HD_ + c];
        Qs[r*132+c+0] = t32(v.x); Qs[r*132+c+1] = t32(v.y);
        Qs[r*132+c+2] = t32(v.z); Qs[r*132+c+3] = t32(v.w);
    }
    const int rrow = tid >> 1;
    const int half = tid & 1;
    const int qi   = row0 + rrow;
    float m_run = -1e30f, l_run = 0.f;
    __syncthreads();

    const int nj = 2 * qb + 2;
    for (int jb = 0; jb < nj; jb++) {
        const int col0 = jb * 64;
#pragma unroll
        for (int it = 0; it < 8; it++) {
            int fid = tid + it * 256;
            int r = fid >> 5, c = (fid & 31) * 4;
            float4 v = *(const float4*)&g_k[(size_t)(col0 + r) * (NKV_*HD_) + kv*HD_ + c];
            Ks[r*132+c+0] = t32(v.x); Ks[r*132+c+1] = t32(v.y);
            Ks[r*132+c+2] = t32(v.z); Ks[r*132+c+3] = t32(v.w);
        }
        __syncthreads();

        wmma::fragment<wmma::accumulator, 16, 16, 8, float> acc[2][2];
#pragma unroll
        for (int i = 0; i < 2; i++)
#pragma unroll
            for (int j = 0; j < 2; j++) wmma::fill_fragment(acc[i][j], 0.0f);
#pragma unroll
        for (int d0 = 0; d0 < HD_; d0 += 8) {
            wmma::fragment<wmma::matrix_a, 16, 16, 8, wmma::precision::tf32, wmma::row_major> af[2];
            wmma::fragment<wmma::matrix_b, 16, 16, 8, wmma::precision::tf32, wmma::col_major> bf[2];
#pragma unroll
            for (int i = 0; i < 2; i++)
                wmma::load_matrix_sync(af[i], &Qs[(wm*32 + i*16)*132 + d0], 132);
#pragma unroll
            for (int j = 0; j < 2; j++)
                wmma::load_matrix_sync(bf[j], &Ks[(wn*32 + j*16)*132 + d0], 132);
#pragma unroll
            for (int i = 0; i < 2; i++)
#pragma unroll
                for (int j = 0; j < 2; j++)
                    wmma::mma_sync(acc[i][j], af[i], bf[j], acc[i][j]);
        }
#pragma unroll
        for (int i = 0; i < 2; i++)
#pragma unroll
            for (int j = 0; j < 2; j++)
                wmma::store_matrix_sync(&Ss[(wm*32 + i*16)*72 + wn*32 + j*16],
                                        acc[i][j], 72, wmma::mem_row_major);
        __syncthreads();

        // online (m, l) update; row owned by thread pair (tid, tid^1)
        const float* srow = &Ss[rrow*72 + half*32];
        const int cb = col0 + half*32;
        float lmax = -1e30f;
#pragma unroll
        for (int c = 0; c < 32; c++) {
            float s = (cb + c <= qi) ? srow[c]*scale : -1e30f;
            lmax = fmaxf(lmax, s);
        }
        lmax = fmaxf(lmax, __shfl_xor_sync(0xffffffffu, lmax, 1));
        float nm = fmaxf(m_run, lmax);
        float ps = 0.f;
#pragma unroll
        for (int c = 0; c < 32; c++) {
            float s = (cb + c <= qi) ? srow[c]*scale : -1e30f;
            ps += __expf(s - nm);
        }
        ps += __shfl_xor_sync(0xffffffffu, ps, 1);
        l_run = l_run * __expf(m_run - nm) + ps;
        m_run = nm;
        __syncthreads();
    }
    if (half == 0) {
        g_m[h*SQ + qi] = m_run;
        g_l[h*SQ + qi] = l_run;
    }
}

// ---------------- zero colsum ----------------
__global__ void zero_colsum()
{
    g_colsum[blockIdx.x * blockDim.x + threadIdx.x] = 0.f;
}

// ---------------- attention pass 2: exact probs -> O + column sums (TF32 wmma) ----------------
#define P2_SMEM ((128*132 + 64*132 + 64*132 + 128*72 + 256) * 4)
__global__ __launch_bounds__(256)
void attn_pass2_t()
{
    extern __shared__ float sm[];
    float* Qs = sm;                  // [128][132]
    float* Ks = Qs + 128*132;        // [64][132]
    float* Vs = Ks + 64*132;         // [64][132]  (k rows, n cols)
    float* Ss = Vs + 64*132;         // [128][72]  S then P
    float* Cs = Ss + 128*72;         // [4][64] colsum partials
    const int qb   = gridDim.x - 1 - blockIdx.x;
    const int h    = blockIdx.y;
    const int kv   = h >> 3;
    const int row0 = qb * 128;
    const int tid  = threadIdx.x;
    const int warp = tid >> 5;
    const int wm = warp >> 1;        // 0..3
    const int wn = warp & 1;         // 0..1
    const float scale = 0.08838834764831845f;

#pragma unroll
    for (int it = 0; it < 16; it++) {
        int fid = tid + it * 256;
        int r = fid >> 5, c = (fid & 31) * 4;
        float4 v = *(const float4*)&g_q[(size_t)(row0 + r) * (NH_*HD_) + h*HD_ + c];
        Qs[r*132+c+0] = t32(v.x); Qs[r*132+c+1] = t32(v.y);
        Qs[r*132+c+2] = t32(v.z); Qs[r*132+c+3] = t32(v.w);
    }
    const int rrow = tid >> 1;
    const int half = tid & 1;
    const int qi   = row0 + rrow;
    const float mr = g_m[h*SQ + qi];
    const float il = 1.0f / g_l[h*SQ + qi];

    // O accumulators: warp rows wm*32 (2 frags), cols wn*64 (4 frags)
    wmma::fragment<wmma::accumulator, 16, 16, 8, float> acc_o[2][4];
#pragma unroll
    for (int i = 0; i < 2; i++)
#pragma unroll
        for (int j = 0; j < 4; j++) wmma::fill_fragment(acc_o[i][j], 0.0f);
    __syncthreads();

    const int nj = 2 * qb + 2;
    for (int jb = 0; jb < nj; jb++) {
        const int col0 = jb * 64;
#pragma unroll
        for (int it = 0; it < 8; it++) {
            int fid = tid + it * 256;
            int r = fid >> 5, c = (fid & 31) * 4;
            float4 k4 = *(const float4*)&g_k[(size_t)(col0 + r) * (NKV_*HD_) + kv*HD_ + c];
            Ks[r*132+c+0] = t32(k4.x); Ks[r*132+c+1] = t32(k4.y);
            Ks[r*132+c+2] = t32(k4.z); Ks[r*132+c+3] = t32(k4.w);
            float4 v4 = *(const float4*)&g_v[(size_t)(col0 + r) * (NKV_*HD_) + kv*HD_ + c];
            Vs[r*132+c+0] = t32(v4.x); Vs[r*132+c+1] = t32(v4.y);
            Vs[r*132+c+2] = t32(v4.z); Vs[r*132+c+3] = t32(v4.w);
        }
        __syncthreads();

        // S = Q K^T
        wmma::fragment<wmma::accumulator, 16, 16, 8, float> acc[2][2];
#pragma unroll
        for (int i = 0; i < 2; i++)
#pragma unroll
            for (int j = 0; j < 2; j++) wmma::fill_fragment(acc[i][j], 0.0f);
#pragma unroll
        for (int d0 = 0; d0 < HD_; d0 += 8) {
            wmma::fragment<wmma::matrix_a, 16, 16, 8, wmma::precision::tf32, wmma::row_major> af[2];
            wmma::fragment<wmma::matrix_b, 16, 16, 8, wmma::precision::tf32, wmma::col_major> bf[2];
#pragma unroll
            for (int i = 0; i < 2; i++)
                wmma::load_matrix_sync(af[i], &Qs[(wm*32 + i*16)*132 + d0], 132);
#pragma unroll
            for (int j = 0; j < 2; j++)
                wmma::load_matrix_sync(bf[j], &Ks[(wn*32 + j*16)*132 + d0], 132);
#pragma unroll
            for (int i = 0; i < 2; i++)
#pragma unroll
                for (int j = 0; j < 2; j++)
                    wmma::mma_sync(acc[i][j], af[i], bf[j], acc[i][j]);
        }
#pragma unroll
        for (int i = 0; i < 2; i++)
#pragma unroll
            for (int j = 0; j < 2; j++)
                wmma::store_matrix_sync(&Ss[(wm*32 + i*16)*72 + wn*32 + j*16],
                                        acc[i][j], 72, wmma::mem_row_major);
        __syncthreads();

        // exact normalized probs in-place (tf32-rounded for PV)
        {
            float* srow = &Ss[rrow*72 + half*32];
            const int cb = col0 + half*32;
#pragma unroll
            for (int c = 0; c < 32; c++) {
                float s = (cb + c <= qi) ? srow[c]*scale : -1e30f;
                srow[c] = t32(__expf(s - mr) * il);
            }
        }
        __syncthreads();

        // column-sum partials (4 segments of 32 rows)
        {
            int col = tid & 63, seg = tid >> 6;
            float cs = 0.f;
#pragma unroll 8
            for (int r = 0; r < 32; r++)
                cs += Ss[(seg*32 + r)*72 + col];
            Cs[seg*64 + col] = cs;
        }
        __syncthreads();
        if (tid < 64)
            atomicAdd(&g_colsum[h*SQ + col0 + tid],
                      Cs[tid] + Cs[64+tid] + Cs[128+tid] + Cs[192+tid]);

        // O += P @ V
#pragma unroll
        for (int k0 = 0; k0 < 64; k0 += 8) {
            wmma::fragment<wmma::matrix_a, 16, 16, 8, wmma::precision::tf32, wmma::row_major> pf[2];
            wmma::fragment<wmma::matrix_b, 16, 16, 8, wmma::precision::tf32, wmma::row_major> vf[4];
#pragma unroll
            for (int i = 0; i < 2; i++)
                wmma::load_matrix_sync(pf[i], &Ss[(wm*32 + i*16)*72 + k0], 72);
#pragma unroll
            for (int j = 0; j < 4; j++)
                wmma::load_matrix_sync(vf[j], &Vs[k0*132 + wn*64 + j*16], 132);
#pragma unroll
            for (int i = 0; i < 2; i++)
#pragma unroll
                for (int j = 0; j < 4; j++)
                    wmma::mma_sync(acc_o[i][j], pf[i], vf[j], acc_o[i][j]);
        }
        __syncthreads();
    }

#pragma unroll
    for (int i = 0; i < 2; i++)
#pragma unroll
        for (int j = 0; j < 4; j++)
            wmma::store_matrix_sync(
                &g_attn[(size_t)(row0 + wm*32 + i*16) * (NH_*HD_) + h*HD_ + wn*64 + j*16],
                acc_o[i][j], NH_*HD_, wmma::mem_row_major);
}

// ---------------- finalize accumulated_scores ----------------
__global__ void finalize_acc(float* __restrict__ out_acc)
{
    int idx = blockIdx.x * blockDim.x + threadIdx.x;  // 0..8191
    int kvh = idx >> 12;
    int col = idx & 4095;
    float s = 0.f;
#pragma unroll
    for (int g = 0; g < GRP_; g++)
        s += g_colsum[(kvh*GRP_ + g)*SQ + col];
    out_acc[idx] = s * 0.125f;
}

// ---------------- launch ----------------
extern "C" void kernel_launch(void* const* d_in, const int* in_sizes, int n_in,
                              void* d_out, int out_size)
{
    const float* hs = (const float*)d_in[0];
    const float* qw = (const float*)d_in[1];
    const float* qbias = (const float*)d_in[2];
    const float* kw = (const float*)d_in[3];
    const float* kbias = (const float*)d_in[4];
    const float* vw = (const float*)d_in[5];
    const float* vbias = (const float*)d_in[6];
    const float* ow = (const float*)d_in[7];
    float* out = (float*)d_out;

    float *qp, *kp, *vp, *ap;
    cudaGetSymbolAddress((void**)&qp, g_q);
    cudaGetSymbolAddress((void**)&kp, g_k);
    cudaGetSymbolAddress((void**)&vp, g_v);
    cudaGetSymbolAddress((void**)&ap, g_attn);

    cudaFuncSetAttribute(attn_pass1_t, cudaFuncAttributeMaxDynamicSharedMemorySize, P1_SMEM);
    cudaFuncSetAttribute(attn_pass2_t, cudaFuncAttributeMaxDynamicSharedMemorySize, P2_SMEM);

    compute_invfreq<<<1, 64>>>();

    // projections (bias folded into rope / bias_v)
    gemm_nt_tf32<<<dim3(16, 32), 256>>>(hs, qw, qp, SQ, NH_*HD_, HID_);
    gemm_nt_tf32<<<dim3(2,  32), 256>>>(hs, kw, kp, SQ, NKV_*HD_, HID_);
    gemm_nt_tf32<<<dim3(2,  32), 256>>>(hs, vw, vp, SQ, NKV_*HD_, HID_);

    rope_bias_kernel<<<(SQ*NH_*64)/256,  256>>>(qp, qbias, NH_,  SQ*NH_*64);
    rope_bias_kernel<<<(SQ*NKV_*64)/256, 256>>>(kp, kbias, NKV_, SQ*NKV_*64);
    bias_v_kernel<<<(SQ*NKV_*HD_)/256, 256>>>(vp, vbias);

    attn_pass1_t<<<dim3(32, 16), 256, P1_SMEM>>>();
    zero_colsum<<<(NH_*SQ)/256, 256>>>();
    attn_pass2_t<<<dim3(32, 16), 256, P2_SMEM>>>();

    // output projection -> first part of d_out
    gemm_nt_tf32<<<dim3(16, 32), 256>>>(ap, ow, out, SQ, HID_, NH_*HD_);
    // accumulated_scores -> tail of d_out
    finalize_acc<<<(NKV_*SQ)/256, 256>>>(out + (out_size - NKV_*SQ));
}

// round 9
// speedup vs baseline: 1.9961x; 1.2974x over previous
#include <cuda_runtime.h>
#include <mma.h>
#include <math.h>
#include <stdint.h>

using namespace nvcuda;

#define SQ    4096
#define NH_   16
#define NKV_  2
#define HD_   128
#define HID_  2048
#define GRP_  8

// ---------------- scratch (device globals; no allocation allowed) ----------------
__device__ float g_q[SQ * NH_ * HD_];      // [s][h*128+d]   (tf32-rounded after rope)
__device__ float g_k[SQ * NKV_ * HD_];
__device__ float g_v[SQ * NKV_ * HD_];
__device__ float g_attn[SQ * NH_ * HD_];   // tf32-rounded at store
__device__ float g_m[NH_ * SQ];
__device__ float g_l[NH_ * SQ];
__device__ float g_colsum[NH_ * SQ];
__device__ float g_invfreq[64];
// tf32-pre-rounded operand copies
__device__ float g_hst[SQ * HID_];
__device__ float g_qwt[NH_ * HD_ * HID_];
__device__ float g_kwt[NKV_ * HD_ * HID_];
__device__ float g_vwt[NKV_ * HD_ * HID_];
__device__ float g_owt[HID_ * NH_ * HD_];

__device__ __forceinline__ float t32(float x) { return wmma::__float_to_tf32(x); }

__device__ __forceinline__ void cp16(void* smem, const void* gmem)
{
    unsigned s = (unsigned)__cvta_generic_to_shared(smem);
    asm volatile("cp.async.cg.shared.global [%0], [%1], 16;\n" :: "r"(s), "l"(gmem));
}
#define CP_COMMIT()  asm volatile("cp.async.commit_group;\n")
#define CP_WAIT(n)   asm volatile("cp.async.wait_group %0;\n" :: "n"(n))

// ---------------- exact inv_freq table ----------------
__global__ void compute_invfreq()
{
    int j = threadIdx.x;
    if (j < 64) g_invfreq[j] = (float)(1.0 / pow(1.0e6, (double)j / 64.0));
}

// ---------------- pre-round to tf32 (vectorized) ----------------
__global__ void copy_round4(float* __restrict__ dst, const float* __restrict__ src, int n4)
{
    int i = blockIdx.x * blockDim.x + threadIdx.x;
    if (i >= n4) return;
    float4 v = ((const float4*)src)[i];
    v.x = t32(v.x); v.y = t32(v.y); v.z = t32(v.z); v.w = t32(v.w);
    ((float4*)dst)[i] = v;
}

// ---------------- pipelined TF32 NT GEMM core ----------------
// BM=BN=128, BK=32, 2-stage cp.async, 256 threads, warp tile 64x32
#define GEMM_SMEM_BYTES (4 * 128 * 36 * 4)
__device__ __forceinline__ void gemm_core(const float* __restrict__ Ag,  // A + row0*K
                                          const float* __restrict__ Bg,  // B + col0*K
                                          float* __restrict__ Cg,        // C tile base
                                          int K, int ldc, bool round_out)
{
    extern __shared__ float sm[];
    float* As = sm;                  // 2 x [128][36]
    float* Bs = sm + 2 * 128 * 36;
    const int tid  = threadIdx.x;
    const int warp = tid >> 5;
    const int wm = warp >> 2;        // 0..1
    const int wn = warp & 3;         // 0..3

    wmma::fragment<wmma::accumulator, 16, 16, 8, float> acc[4][2];
#pragma unroll
    for (int i = 0; i < 4; i++)
#pragma unroll
        for (int j = 0; j < 2; j++) wmma::fill_fragment(acc[i][j], 0.0f);

    const int nk = K >> 5;
    // preload stage 0
    {
        float* Ad = As; float* Bd = Bs;
#pragma unroll
        for (int it = 0; it < 4; it++) {
            int fid = tid + it * 256;
            int r = fid >> 3, c = (fid & 7) * 4;
            cp16(&Ad[r*36 + c], &Ag[(size_t)r * K + c]);
            cp16(&Bd[r*36 + c], &Bg[(size_t)r * K + c]);
        }
        CP_COMMIT();
    }
    for (int t = 0; t < nk; t++) {
        if (t + 1 < nk) {
            int k0 = (t + 1) << 5;
            float* Ad = As + ((t+1)&1) * 128*36;
            float* Bd = Bs + ((t+1)&1) * 128*36;
#pragma unroll
            for (int it = 0; it < 4; it++) {
                int fid = tid + it * 256;
                int r = fid >> 3, c = (fid & 7) * 4;
                cp16(&Ad[r*36 + c], &Ag[(size_t)r * K + k0 + c]);
                cp16(&Bd[r*36 + c], &Bg[(size_t)r * K + k0 + c]);
            }
            CP_COMMIT();
            CP_WAIT(1);
        } else {
            CP_WAIT(0);
        }
        __syncthreads();
        const float* Ab = As + (t&1) * 128*36;
        const float* Bb = Bs + (t&1) * 128*36;
#pragma unroll
        for (int kk = 0; kk < 32; kk += 8) {
            wmma::fragment<wmma::matrix_a, 16, 16, 8, wmma::precision::tf32, wmma::row_major> af[4];
            wmma::fragment<wmma::matrix_b, 16, 16, 8, wmma::precision::tf32, wmma::col_major> bf[2];
#pragma unroll
            for (int i = 0; i < 4; i++)
                wmma::load_matrix_sync(af[i], &Ab[(wm*64 + i*16)*36 + kk], 36);
#pragma unroll
            for (int j = 0; j < 2; j++)
                wmma::load_matrix_sync(bf[j], &Bb[(wn*32 + j*16)*36 + kk], 36);
#pragma unroll
            for (int i = 0; i < 4; i++)
#pragma unroll
                for (int j = 0; j < 2; j++)
                    wmma::mma_sync(acc[i][j], af[i], bf[j], acc[i][j]);
        }
        __syncthreads();
    }
    if (round_out) {
#pragma unroll
        for (int i = 0; i < 4; i++)
#pragma unroll
            for (int j = 0; j < 2; j++)
#pragma unroll
                for (int e = 0; e < acc[i][j].num_elements; e++)
                    acc[i][j].x[e] = t32(acc[i][j].x[e]);
    }
#pragma unroll
    for (int i = 0; i < 4; i++)
#pragma unroll
        for (int j = 0; j < 2; j++)
            wmma::store_matrix_sync(&Cg[(size_t)(wm*64 + i*16) * ldc + wn*32 + j*16],
                                    acc[i][j], ldc, wmma::mem_row_major);
}

// fused QKV projection: grid (20, 32)
__global__ __launch_bounds__(256, 2) void gemm_qkv()
{
    const int nt = blockIdx.x, mt = blockIdx.y;
    const float* B; float* Cb; int ldc;
    if (nt < 16)      { B = g_qwt + (size_t)nt*128*HID_;      Cb = g_q + (size_t)mt*128*(NH_*HD_)  + nt*128;      ldc = NH_*HD_; }
    else if (nt < 18) { B = g_kwt + (size_t)(nt-16)*128*HID_; Cb = g_k + (size_t)mt*128*(NKV_*HD_) + (nt-16)*128; ldc = NKV_*HD_; }
    else              { B = g_vwt + (size_t)(nt-18)*128*HID_; Cb = g_v + (size_t)mt*128*(NKV_*HD_) + (nt-18)*128; ldc = NKV_*HD_; }
    gemm_core(g_hst + (size_t)mt*128*HID_, B, Cb, HID_, ldc, false);
}

// output projection: grid (16, 32)
__global__ __launch_bounds__(256, 2) void gemm_o(float* __restrict__ out)
{
    const int nt = blockIdx.x, mt = blockIdx.y;
    gemm_core(g_attn + (size_t)mt*128*(NH_*HD_),
              g_owt  + (size_t)nt*128*(NH_*HD_),
              out    + (size_t)mt*128*HID_ + nt*128,
              NH_*HD_, HID_, false);
}

// ---------------- RoPE in-place with fused bias add; rounds output to tf32 ----------------
__global__ void rope_bias_kernel(float* __restrict__ x, const float* __restrict__ bias,
                                 int nheads, int total)
{
    int idx = blockIdx.x * blockDim.x + threadIdx.x;
    if (idx >= total) return;
    int j = idx & 63;
    int h = (idx >> 6) % nheads;
    int s = (idx >> 6) / nheads;
    float fr = (float)s * g_invfreq[j];
    float c, sn;
    sincosf(fr, &sn, &c);
    float* p = x + (size_t)s * nheads * HD_ + h * HD_;
    float x1 = p[j]      + bias[h*HD_ + j];
    float x2 = p[j + 64] + bias[h*HD_ + j + 64];
    p[j]      = t32(x1 * c - x2 * sn);
    p[j + 64] = t32(x2 * c + x1 * sn);
}

// ---------------- V bias add (rounds output) ----------------
__global__ void bias_v_kernel(float* __restrict__ v, const float* __restrict__ b)
{
    int i = blockIdx.x * blockDim.x + threadIdx.x;
    v[i] = t32(v[i] + b[i & (NKV_*HD_ - 1)]);
}

// ---------------- attention pass 1: per-row max + sum-exp ----------------
#define P1_SMEM ((128*132 + 2*64*132 + 128*68) * 4)
__global__ __launch_bounds__(256, 1) void attn_pass1_t()
{
    extern __shared__ float sm[];
    float* Qs = sm;                  // [128][132]
    float* Ks = Qs + 128*132;        // 2 x [64][132]
    float* Ss = Ks + 2*64*132;       // [128][68]
    const int qb   = gridDim.x - 1 - blockIdx.x;
    const int h    = blockIdx.y;
    const int kv   = h >> 3;
    const int row0 = qb * 128;
    const int tid  = threadIdx.x;
    const int warp = tid >> 5;
    const int wm = warp >> 1;        // 0..3
    const int wn = warp & 1;         // 0..1
    const float scale = 0.08838834764831845f;

    // stage Q (already tf32-rounded)
#pragma unroll
    for (int it = 0; it < 16; it++) {
        int fid = tid + it * 256;
        int r = fid >> 5, c = (fid & 31) * 4;
        *(float4*)&Qs[r*132 + c] =
            *(const float4*)&g_q[(size_t)(row0 + r) * (NH_*HD_) + h*HD_ + c];
    }
    const int rrow = tid >> 1;
    const int half = tid & 1;
    const int qi   = row0 + rrow;
    float m_run = -1e30f, l_run = 0.f;

    const int nj = 2 * qb + 2;
    // preload K tile 0
    {
#pragma unroll
        for (int it = 0; it < 8; it++) {
            int fid = tid + it * 256;
            int r = fid >> 5, c = (fid & 31) * 4;
            cp16(&Ks[r*132 + c], &g_k[(size_t)r * (NKV_*HD_) + kv*HD_ + c]);
        }
        CP_COMMIT();
    }
    __syncthreads();

    for (int jb = 0; jb < nj; jb++) {
        if (jb + 1 < nj) {
            float* dst = Ks + ((jb+1)&1) * 64*132;
            int col0n = (jb+1) * 64;
#pragma unroll
            for (int it = 0; it < 8; it++) {
                int fid = tid + it * 256;
                int r = fid >> 5, c = (fid & 31) * 4;
                cp16(&dst[r*132 + c], &g_k[(size_t)(col0n + r) * (NKV_*HD_) + kv*HD_ + c]);
            }
            CP_COMMIT();
            CP_WAIT(1);
        } else {
            CP_WAIT(0);
        }
        __syncthreads();
        const float* Kb = Ks + (jb&1) * 64*132;

        wmma::fragment<wmma::accumulator, 16, 16, 8, float> acc[2][2];
#pragma unroll
        for (int i = 0; i < 2; i++)
#pragma unroll
            for (int j = 0; j < 2; j++) wmma::fill_fragment(acc[i][j], 0.0f);
#pragma unroll
        for (int d0 = 0; d0 < HD_; d0 += 8) {
            wmma::fragment<wmma::matrix_a, 16, 16, 8, wmma::precision::tf32, wmma::row_major> af[2];
            wmma::fragment<wmma::matrix_b, 16, 16, 8, wmma::precision::tf32, wmma::col_major> bf[2];
#pragma unroll
            for (int i = 0; i < 2; i++)
                wmma::load_matrix_sync(af[i], &Qs[(wm*32 + i*16)*132 + d0], 132);
#pragma unroll
            for (int j = 0; j < 2; j++)
                wmma::load_matrix_sync(bf[j], &Kb[(wn*32 + j*16)*132 + d0], 132);
#pragma unroll
            for (int i = 0; i < 2; i++)
#pragma unroll
                for (int j = 0; j < 2; j++)
                    wmma::mma_sync(acc[i][j], af[i], bf[j], acc[i][j]);
        }
#pragma unroll
        for (int i = 0; i < 2; i++)
#pragma unroll
            for (int j = 0; j < 2; j++)
                wmma::store_matrix_sync(&Ss[(wm*32 + i*16)*68 + wn*32 + j*16],
                                        acc[i][j], 68, wmma::mem_row_major);
        __syncthreads();

        const float* srow = &Ss[rrow*68 + half*32];
        const int cb = jb*64 + half*32;
        float lmax = -1e30f;
#pragma unroll
        for (int c = 0; c < 32; c++) {
            float s = (cb + c <= qi) ? srow[c]*scale : -1e30f;
            lmax = fmaxf(lmax, s);
        }
        lmax = fmaxf(lmax, __shfl_xor_sync(0xffffffffu, lmax, 1));
        float nm = fmaxf(m_run, lmax);
        float ps = 0.f;
#pragma unroll
        for (int c = 0; c < 32; c++) {
            float s = (cb + c <= qi) ? srow[c]*scale : -1e30f;
            ps += __expf(s - nm);
        }
        ps += __shfl_xor_sync(0xffffffffu, ps, 1);
        l_run = l_run * __expf(m_run - nm) + ps;
        m_run = nm;
        __syncthreads();
    }
    if (half == 0) {
        g_m[h*SQ + qi] = m_run;
        g_l[h*SQ + qi] = l_run;
    }
}

// ---------------- zero colsum ----------------
__global__ void zero_colsum()
{
    g_colsum[blockIdx.x * blockDim.x + threadIdx.x] = 0.f;
}

// ---------------- attention pass 2: exact probs -> O + column sums ----------------
#define P2_SMEM ((128*132 + 2*64*132 + 64*132 + 128*68 + 256) * 4)
__global__ __launch_bounds__(256, 1) void attn_pass2_t()
{
    extern __shared__ float sm[];
    float* Qs = sm;                  // [128][132]
    float* Ks = Qs + 128*132;        // 2 x [64][132]
    float* Vs = Ks + 2*64*132;       // [64][132]
    float* Ss = Vs + 64*132;         // [128][68]
    float* Cs = Ss + 128*68;         // [4][64]
    const int qb   = gridDim.x - 1 - blockIdx.x;
    const int h    = blockIdx.y;
    const int kv   = h >> 3;
    const int row0 = qb * 128;
    const int tid  = threadIdx.x;
    const int warp = tid >> 5;
    const int wm = warp >> 1;        // 0..3
    const int wn = warp & 1;         // 0..1
    const float scale = 0.08838834764831845f;

#pragma unroll
    for (int it = 0; it < 16; it++) {
        int fid = tid + it * 256;
        int r = fid >> 5, c = (fid & 31) * 4;
        *(float4*)&Qs[r*132 + c] =
            *(const float4*)&g_q[(size_t)(row0 + r) * (NH_*HD_) + h*HD_ + c];
    }
    const int rrow = tid >> 1;
    const int half = tid & 1;
    const int qi   = row0 + rrow;
    const float mr = g_m[h*SQ + qi];
    const float il = 1.0f / g_l[h*SQ + qi];

    wmma::fragment<wmma::accumulator, 16, 16, 8, float> acc_o[2][4];
#pragma unroll
    for (int i = 0; i < 2; i++)
#pragma unroll
        for (int j = 0; j < 4; j++) wmma::fill_fragment(acc_o[i][j], 0.0f);

    const int nj = 2 * qb + 2;
    // preload K tile 0 (group 0)
    {
#pragma unroll
        for (int it = 0; it < 8; it++) {
            int fid = tid + it * 256;
            int r = fid >> 5, c = (fid & 31) * 4;
            cp16(&Ks[r*132 + c], &g_k[(size_t)r * (NKV_*HD_) + kv*HD_ + c]);
        }
        CP_COMMIT();
    }
    __syncthreads();

    for (int jb = 0; jb < nj; jb++) {
        const int col0 = jb * 64;
        // issue V(jb) prefetch (single buffer; prior PV reads fenced by loop-end barrier)
        {
#pragma unroll
            for (int it = 0; it < 8; it++) {
                int fid = tid + it * 256;
                int r = fid >> 5, c = (fid & 31) * 4;
                cp16(&Vs[r*132 + c], &g_v[(size_t)(col0 + r) * (NKV_*HD_) + kv*HD_ + c]);
            }
            CP_COMMIT();
        }
        CP_WAIT(1);                  // K(jb) done (pending: V(jb))
        __syncthreads();
        const float* Kb = Ks + (jb&1) * 64*132;

        // S = Q K^T
        wmma::fragment<wmma::accumulator, 16, 16, 8, float> acc[2][2];
#pragma unroll
        for (int i = 0; i < 2; i++)
#pragma unroll
            for (int j = 0; j < 2; j++) wmma::fill_fragment(acc[i][j], 0.0f);
#pragma unroll
        for (int d0 = 0; d0 < HD_; d0 += 8) {
            wmma::fragment<wmma::matrix_a, 16, 16, 8, wmma::precision::tf32, wmma::row_major> af[2];
            wmma::fragment<wmma::matrix_b, 16, 16, 8, wmma::precision::tf32, wmma::col_major> bf[2];
#pragma unroll
            for (int i = 0; i < 2; i++)
                wmma::load_matrix_sync(af[i], &Qs[(wm*32 + i*16)*132 + d0], 132);
#pragma unroll
            for (int j = 0; j < 2; j++)
                wmma::load_matrix_sync(bf[j], &Kb[(wn*32 + j*16)*132 + d0], 132);
#pragma unroll
            for (int i = 0; i < 2; i++)
#pragma unroll
                for (int j = 0; j < 2; j++)
                    wmma::mma_sync(acc[i][j], af[i], bf[j], acc[i][j]);
        }
#pragma unroll
        for (int i = 0; i < 2; i++)
#pragma unroll
            for (int j = 0; j < 2; j++)
                wmma::store_matrix_sync(&Ss[(wm*32 + i*16)*68 + wn*32 + j*16],
                                        acc[i][j], 68, wmma::mem_row_major);
        __syncthreads();

        // exact normalized probs in-place (rounded for PV)
        {
            float* srow = &Ss[rrow*68 + half*32];
            const int cb = col0 + half*32;
#pragma unroll
            for (int c = 0; c < 32; c++) {
                float s = (cb + c <= qi) ? srow[c]*scale : -1e30f;
                srow[c] = t32(__expf(s - mr) * il);
            }
        }

        // issue K(jb+1) prefetch
        if (jb + 1 < nj) {
            float* dst = Ks + ((jb+1)&1) * 64*132;
            int col0n = (jb+1) * 64;
#pragma unroll
            for (int it = 0; it < 8; it++) {
                int fid = tid + it * 256;
                int r = fid >> 5, c = (fid & 31) * 4;
                cp16(&dst[r*132 + c], &g_k[(size_t)(col0n + r) * (NKV_*HD_) + kv*HD_ + c]);
            }
            CP_COMMIT();
            CP_WAIT(1);              // V(jb) done (pending: K(jb+1))
        } else {
            CP_WAIT(0);              // V(jb) done
        }
        __syncthreads();             // V visible + probs visible to all

        // column-sum partials
        {
            int col = tid & 63, seg = tid >> 6;
            float cs = 0.f;
#pragma unroll 8
            for (int r = 0; r < 32; r++)
                cs += Ss[(seg*32 + r)*68 + col];
            Cs[seg*64 + col] = cs;
        }
        __syncthreads();
        if (tid < 64)
            atomicAdd(&g_colsum[h*SQ + col0 + tid],
                      Cs[tid] + Cs[64+tid] + Cs[128+tid] + Cs[192+tid]);

        // O += P @ V
#pragma unroll
        for (int k0 = 0; k0 < 64; k0 += 8) {
            wmma::fragment<wmma::matrix_a, 16, 16, 8, wmma::precision::tf32, wmma::row_major> pf[2];
            wmma::fragment<wmma::matrix_b, 16, 16, 8, wmma::precision::tf32, wmma::row_major> vf[4];
#pragma unroll
            for (int i = 0; i < 2; i++)
                wmma::load_matrix_sync(pf[i], &Ss[(wm*32 + i*16)*68 + k0], 68);
#pragma unroll
            for (int j = 0; j < 4; j++)
                wmma::load_matrix_sync(vf[j], &Vs[k0*132 + wn*64 + j*16], 132);
#pragma unroll
            for (int i = 0; i < 2; i++)
#pragma unroll
                for (int j = 0; j < 4; j++)
                    wmma::mma_sync(acc_o[i][j], pf[i], vf[j], acc_o[i][j]);
        }
        __syncthreads();             // before V(jb+1) overwrite & Ss reuse
    }

    // round O for the O-projection's tensor path, then store
#pragma unroll
    for (int i = 0; i < 2; i++)
#pragma unroll
        for (int j = 0; j < 4; j++) {
#pragma unroll
            for (int e = 0; e < acc_o[i][j].num_elements; e++)
                acc_o[i][j].x[e] = t32(acc_o[i][j].x[e]);
            wmma::store_matrix_sync(
                &g_attn[(size_t)(row0 + wm*32 + i*16) * (NH_*HD_) + h*HD_ + wn*64 + j*16],
                acc_o[i][j], NH_*HD_, wmma::mem_row_major);
        }
}

// ---------------- finalize accumulated_scores ----------------
__global__ void finalize_acc(float* __restrict__ out_acc)
{
    int idx = blockIdx.x * blockDim.x + threadIdx.x;  // 0..8191
    int kvh = idx >> 12;
    int col = idx & 4095;
    float s = 0.f;
#pragma unroll
    for (int g = 0; g < GRP_; g++)
        s += g_colsum[(kvh*GRP_ + g)*SQ + col];
    out_acc[idx] = s * 0.125f;
}

// ---------------- launch ----------------
extern "C" void kernel_launch(void* const* d_in, const int* in_sizes, int n_in,
                              void* d_out, int out_size)
{
    const float* hs = (const float*)d_in[0];
    const float* qw = (const float*)d_in[1];
    const float* qbias = (const float*)d_in[2];
    const float* kw = (const float*)d_in[3];
    const float* kbias = (const float*)d_in[4];
    const float* vw = (const float*)d_in[5];
    const float* vbias = (const float*)d_in[6];
    const float* ow = (const float*)d_in[7];
    float* out = (float*)d_out;

    float *qp, *kp, *vp;
    float *hst, *qwt, *kwt, *vwt, *owt;
    cudaGetSymbolAddress((void**)&qp, g_q);
    cudaGetSymbolAddress((void**)&kp, g_k);
    cudaGetSymbolAddress((void**)&vp, g_v);
    cudaGetSymbolAddress((void**)&hst, g_hst);
    cudaGetSymbolAddress((void**)&qwt, g_qwt);
    cudaGetSymbolAddress((void**)&kwt, g_kwt);
    cudaGetSymbolAddress((void**)&vwt, g_vwt);
    cudaGetSymbolAddress((void**)&owt, g_owt);

    cudaFuncSetAttribute(gemm_qkv, cudaFuncAttributeMaxDynamicSharedMemorySize, GEMM_SMEM_BYTES);
    cudaFuncSetAttribute(gemm_o,   cudaFuncAttributeMaxDynamicSharedMemorySize, GEMM_SMEM_BYTES);
    cudaFuncSetAttribute(attn_pass1_t, cudaFuncAttributeMaxDynamicSharedMemorySize, P1_SMEM);
    cudaFuncSetAttribute(attn_pass2_t, cudaFuncAttributeMaxDynamicSharedMemorySize, P2_SMEM);

    compute_invfreq<<<1, 64>>>();

    // pre-round all tensor operands once
    copy_round4<<<(SQ*HID_/4 + 255)/256, 256>>>(hst, hs, SQ*HID_/4);
    copy_round4<<<(NH_*HD_*HID_/4 + 255)/256, 256>>>(qwt, qw, NH_*HD_*HID_/4);
    copy_round4<<<(NKV_*HD_*HID_/4 + 255)/256, 256>>>(kwt, kw, NKV_*HD_*HID_/4);
    copy_round4<<<(NKV_*HD_*HID_/4 + 255)/256, 256>>>(vwt, vw, NKV_*HD_*HID_/4);
    copy_round4<<<(HID_*NH_*HD_/4 + 255)/256, 256>>>(owt, ow, HID_*NH_*HD_/4);

    // fused QKV projection
    gemm_qkv<<<dim3(20, 32), 256, GEMM_SMEM_BYTES>>>();

    rope_bias_kernel<<<(SQ*NH_*64)/256,  256>>>(qp, qbias, NH_,  SQ*NH_*64);
    rope_bias_kernel<<<(SQ*NKV_*64)/256, 256>>>(kp, kbias, NKV_, SQ*NKV_*64);
    bias_v_kernel<<<(SQ*NKV_*HD_)/256, 256>>>(vp, vbias);

    attn_pass1_t<<<dim3(32, 16), 256, P1_SMEM>>>();
    zero_colsum<<<(NH_*SQ)/256, 256>>>();
    attn_pass2_t<<<dim3(32, 16), 256, P2_SMEM>>>();

    gemm_o<<<dim3(16, 32), 256, GEMM_SMEM_BYTES>>>(out);
    finalize_acc<<<(NKV_*SQ)/256, 256>>>(out + (out_size - NKV_*SQ));
}

// round 13
// speedup vs baseline: 2.3975x; 1.2011x over previous
#include <cuda_runtime.h>
#include <mma.h>
#include <math.h>
#include <stdint.h>

using namespace nvcuda;

#define SQ    4096
#define NH_   16
#define NKV_  2
#define HD_   128
#define HID_  2048
#define GRP_  8
// per-head causal-packed S scratch: sum_qb 128*(qb+1)*128 = 16384*528
#define STOT  8650752

// ---------------- scratch (device globals; no allocation allowed) ----------------
__device__ float g_q[SQ * NH_ * HD_];      // [s][h*128+d]   (tf32-rounded after rope)
__device__ float g_k[SQ * NKV_ * HD_];
__device__ float g_v[SQ * NKV_ * HD_];
__device__ float g_attn[SQ * NH_ * HD_];   // tf32-rounded at store
__device__ float g_m[NH_ * SQ];
__device__ float g_l[NH_ * SQ];
__device__ float g_colsum[NH_ * SQ];
__device__ float g_invfreq[64];
// tf32-pre-rounded operand copies
__device__ float g_hst[SQ * HID_];
__device__ float g_qwt[NH_ * HD_ * HID_];
__device__ float g_kwt[NKV_ * HD_ * HID_];
__device__ float g_vwt[NKV_ * HD_ * HID_];
__device__ float g_owt[HID_ * NH_ * HD_];
// materialized raw attention logits (pre-scale), causal-packed
__device__ float g_s[(size_t)NH_ * STOT];

__device__ __forceinline__ float t32(float x) { return wmma::__float_to_tf32(x); }

__device__ __forceinline__ void cp16(void* smem, const void* gmem)
{
    unsigned s = (unsigned)__cvta_generic_to_shared(smem);
    asm volatile("cp.async.cg.shared.global [%0], [%1], 16;\n" :: "r"(s), "l"(gmem));
}
#define CP_COMMIT()  asm volatile("cp.async.commit_group;\n")
#define CP_WAIT(n)   asm volatile("cp.async.wait_group %0;\n" :: "n"(n))

// ---------------- exact inv_freq table ----------------
__global__ void compute_invfreq()
{
    int j = threadIdx.x;
    if (j < 64) g_invfreq[j] = (float)(1.0 / pow(1.0e6, (double)j / 64.0));
}

// ---------------- pre-round to tf32 (vectorized) ----------------
__global__ void copy_round4(float* __restrict__ dst, const float* __restrict__ src, int n4)
{
    int i = blockIdx.x * blockDim.x + threadIdx.x;
    if (i >= n4) return;
    float4 v = ((const float4*)src)[i];
    v.x = t32(v.x); v.y = t32(v.y); v.z = t32(v.z); v.w = t32(v.w);
    ((float4*)dst)[i] = v;
}

// ---------------- pipelined TF32 NT GEMM core ----------------
// BM=BN=128, BK=32, 2-stage cp.async, 256 threads, warp tile 64x32
#define GEMM_SMEM_BYTES (4 * 128 * 36 * 4)
__device__ __forceinline__ void gemm_core(const float* __restrict__ Ag,
                                          const float* __restrict__ Bg,
                                          float* __restrict__ Cg,
                                          int K, int ldc)
{
    extern __shared__ float sm[];
    float* As = sm;                  // 2 x [128][36]
    float* Bs = sm + 2 * 128 * 36;
    const int tid  = threadIdx.x;
    const int warp = tid >> 5;
    const int wm = warp >> 2;        // 0..1
    const int wn = warp & 3;         // 0..3

    wmma::fragment<wmma::accumulator, 16, 16, 8, float> acc[4][2];
#pragma unroll
    for (int i = 0; i < 4; i++)
#pragma unroll
        for (int j = 0; j < 2; j++) wmma::fill_fragment(acc[i][j], 0.0f);

    const int nk = K >> 5;
    {
        float* Ad = As; float* Bd = Bs;
#pragma unroll
        for (int it = 0; it < 4; it++) {
            int fid = tid + it * 256;
            int r = fid >> 3, c = (fid & 7) * 4;
            cp16(&Ad[r*36 + c], &Ag[(size_t)r * K + c]);
            cp16(&Bd[r*36 + c], &Bg[(size_t)r * K + c]);
        }
        CP_COMMIT();
    }
    for (int t = 0; t < nk; t++) {
        if (t + 1 < nk) {
            int k0 = (t + 1) << 5;
            float* Ad = As + ((t+1)&1) * 128*36;
            float* Bd = Bs + ((t+1)&1) * 128*36;
#pragma unroll
            for (int it = 0; it < 4; it++) {
                int fid = tid + it * 256;
                int r = fid >> 3, c = (fid & 7) * 4;
                cp16(&Ad[r*36 + c], &Ag[(size_t)r * K + k0 + c]);
                cp16(&Bd[r*36 + c], &Bg[(size_t)r * K + k0 + c]);
            }
            CP_COMMIT();
            CP_WAIT(1);
        } else {
            CP_WAIT(0);
        }
        __syncthreads();
        const float* Ab = As + (t&1) * 128*36;
        const float* Bb = Bs + (t&1) * 128*36;
#pragma unroll
        for (int kk = 0; kk < 32; kk += 8) {
            wmma::fragment<wmma::matrix_a, 16, 16, 8, wmma::precision::tf32, wmma::row_major> af[4];
            wmma::fragment<wmma::matrix_b, 16, 16, 8, wmma::precision::tf32, wmma::col_major> bf[2];
#pragma unroll
            for (int i = 0; i < 4; i++)
                wmma::load_matrix_sync(af[i], &Ab[(wm*64 + i*16)*36 + kk], 36);
#pragma unroll
            for (int j = 0; j < 2; j++)
                wmma::load_matrix_sync(bf[j], &Bb[(wn*32 + j*16)*36 + kk], 36);
#pragma unroll
            for (int i = 0; i < 4; i++)
#pragma unroll
                for (int j = 0; j < 2; j++)
                    wmma::mma_sync(acc[i][j], af[i], bf[j], acc[i][j]);
        }
        __syncthreads();
    }
#pragma unroll
    for (int i = 0; i < 4; i++)
#pragma unroll
        for (int j = 0; j < 2; j++)
            wmma::store_matrix_sync(&Cg[(size_t)(wm*64 + i*16) * ldc + wn*32 + j*16],
                                    acc[i][j], ldc, wmma::mem_row_major);
}

// fused QKV projection: grid (20, 32)
__global__ __launch_bounds__(256, 2) void gemm_qkv()
{
    const int nt = blockIdx.x, mt = blockIdx.y;
    const float* B; float* Cb; int ldc;
    if (nt < 16)      { B = g_qwt + (size_t)nt*128*HID_;      Cb = g_q + (size_t)mt*128*(NH_*HD_)  + nt*128;      ldc = NH_*HD_; }
    else if (nt < 18) { B = g_kwt + (size_t)(nt-16)*128*HID_; Cb = g_k + (size_t)mt*128*(NKV_*HD_) + (nt-16)*128; ldc = NKV_*HD_; }
    else              { B = g_vwt + (size_t)(nt-18)*128*HID_; Cb = g_v + (size_t)mt*128*(NKV_*HD_) + (nt-18)*128; ldc = NKV_*HD_; }
    gemm_core(g_hst + (size_t)mt*128*HID_, B, Cb, HID_, ldc);
}

// output projection: grid (16, 32)
__global__ __launch_bounds__(256, 2) void gemm_o(float* __restrict__ out)
{
    const int nt = blockIdx.x, mt = blockIdx.y;
    gemm_core(g_attn + (size_t)mt*128*(NH_*HD_),
              g_owt  + (size_t)nt*128*(NH_*HD_),
              out    + (size_t)mt*128*HID_ + nt*128,
              NH_*HD_, HID_);
}

// ---------------- RoPE in-place with fused bias add; rounds output to tf32 ----------------
__global__ void rope_bias_kernel(float* __restrict__ x, const float* __restrict__ bias,
                                 int nheads, int total)
{
    int idx = blockIdx.x * blockDim.x + threadIdx.x;
    if (idx >= total) return;
    int j = idx & 63;
    int h = (idx >> 6) % nheads;
    int s = (idx >> 6) / nheads;
    float fr = (float)s * g_invfreq[j];
    float c, sn;
    sincosf(fr, &sn, &c);
    float* p = x + (size_t)s * nheads * HD_ + h * HD_;
    float x1 = p[j]      + bias[h*HD_ + j];
    float x2 = p[j + 64] + bias[h*HD_ + j + 64];
    p[j]      = t32(x1 * c - x2 * sn);
    p[j + 64] = t32(x2 * c + x1 * sn);
}

// ---------------- V bias add (rounds output) ----------------
__global__ void bias_v_kernel(float* __restrict__ v, const float* __restrict__ b)
{
    int i = blockIdx.x * blockDim.x + threadIdx.x;
    v[i] = t32(v[i] + b[i & (NKV_*HD_ - 1)]);
}

// ---------------- attention pass 1: per-row max + sum-exp; stores raw S tiles ----------------
#define P1_SMEM ((128*132 + 2*64*132 + 128*68) * 4)
__global__ __launch_bounds__(256, 1) void attn_pass1_t()
{
    extern __shared__ float sm[];
    float* Qs = sm;                  // [128][132]
    float* Ks = Qs + 128*132;        // 2 x [64][132]
    float* Ss = Ks + 2*64*132;       // [128][68]
    const int qb   = gridDim.x - 1 - blockIdx.x;
    const int h    = blockIdx.y;
    const int kv   = h >> 3;
    const int row0 = qb * 128;
    const int tid  = threadIdx.x;
    const int warp = tid >> 5;
    const int wm = warp >> 1;        // 0..3
    const int wn = warp & 1;         // 0..1
    const float scale = 0.08838834764831845f;
    const int ncols = (qb + 1) * 128;
    const size_t sbase = (size_t)h * STOT + (size_t)16384 * ((size_t)qb * (qb + 1) / 2);

    // stage Q (already tf32-rounded)
#pragma unroll
    for (int it = 0; it < 16; it++) {
        int fid = tid + it * 256;
        int r = fid >> 5, c = (fid & 31) * 4;
        *(float4*)&Qs[r*132 + c] =
            *(const float4*)&g_q[(size_t)(row0 + r) * (NH_*HD_) + h*HD_ + c];
    }
    const int rrow = tid >> 1;
    const int half = tid & 1;
    const int qi   = row0 + rrow;
    float m_run = -1e30f, l_run = 0.f;

    const int nj = 2 * qb + 2;
    // preload K tile 0
    {
#pragma unroll
        for (int it = 0; it < 8; it++) {
            int fid = tid + it * 256;
            int r = fid >> 5, c = (fid & 31) * 4;
            cp16(&Ks[r*132 + c], &g_k[(size_t)r * (NKV_*HD_) + kv*HD_ + c]);
        }
        CP_COMMIT();
    }
    __syncthreads();

    for (int jb = 0; jb < nj; jb++) {
        if (jb + 1 < nj) {
            float* dst = Ks + ((jb+1)&1) * 64*132;
            int col0n = (jb+1) * 64;
#pragma unroll
            for (int it = 0; it < 8; it++) {
                int fid = tid + it * 256;
                int r = fid >> 5, c = (fid & 31) * 4;
                cp16(&dst[r*132 + c], &g_k[(size_t)(col0n + r) * (NKV_*HD_) + kv*HD_ + c]);
            }
            CP_COMMIT();
            CP_WAIT(1);
        } else {
            CP_WAIT(0);
        }
        __syncthreads();
        const float* Kb = Ks + (jb&1) * 64*132;

        wmma::fragment<wmma::accumulator, 16, 16, 8, float> acc[2][2];
#pragma unroll
        for (int i = 0; i < 2; i++)
#pragma unroll
            for (int j = 0; j < 2; j++) wmma::fill_fragment(acc[i][j], 0.0f);
#pragma unroll
        for (int d0 = 0; d0 < HD_; d0 += 8) {
            wmma::fragment<wmma::matrix_a, 16, 16, 8, wmma::precision::tf32, wmma::row_major> af[2];
            wmma::fragment<wmma::matrix_b, 16, 16, 8, wmma::precision::tf32, wmma::col_major> bf[2];
#pragma unroll
            for (int i = 0; i < 2; i++)
                wmma::load_matrix_sync(af[i], &Qs[(wm*32 + i*16)*132 + d0], 132);
#pragma unroll
            for (int j = 0; j < 2; j++)
                wmma::load_matrix_sync(bf[j], &Kb[(wn*32 + j*16)*132 + d0], 132);
#pragma unroll
            for (int i = 0; i < 2; i++)
#pragma unroll
                for (int j = 0; j < 2; j++)
                    wmma::mma_sync(acc[i][j], af[i], bf[j], acc[i][j]);
        }
#pragma unroll
        for (int i = 0; i < 2; i++)
#pragma unroll
            for (int j = 0; j < 2; j++)
                wmma::store_matrix_sync(&Ss[(wm*32 + i*16)*68 + wn*32 + j*16],
                                        acc[i][j], 68, wmma::mem_row_major);
        __syncthreads();

        // online (m, l) stats
        {
            const float* srow = &Ss[rrow*68 + half*32];
            const int cb = jb*64 + half*32;
            float lmax = -1e30f;
#pragma unroll
            for (int c = 0; c < 32; c++) {
                float s = (cb + c <= qi) ? srow[c]*scale : -1e30f;
                lmax = fmaxf(lmax, s);
            }
            lmax = fmaxf(lmax, __shfl_xor_sync(0xffffffffu, lmax, 1));
            float nm = fmaxf(m_run, lmax);
            float ps = 0.f;
#pragma unroll
            for (int c = 0; c < 32; c++) {
                float s = (cb + c <= qi) ? srow[c]*scale : -1e30f;
                ps += __expf(s - nm);
            }
            ps += __shfl_xor_sync(0xffffffffu, ps, 1);
            l_run = l_run * __expf(m_run - nm) + ps;
            m_run = nm;
        }

        // write raw S tile to gmem for pass2 (128 x 64)
        {
            float* dst = g_s + sbase + (size_t)jb * 64;
#pragma unroll
            for (int it = 0; it < 8; it++) {
                int fid = tid + it * 256;
                int r = fid >> 4, c = (fid & 15) * 4;
                *(float4*)&dst[(size_t)r * ncols + c] = *(const float4*)&Ss[r*68 + c];
            }
        }
        __syncthreads();
    }
    if (half == 0) {
        g_m[h*SQ + qi] = m_run;
        g_l[h*SQ + qi] = l_run;
    }
}

// ---------------- zero colsum ----------------
__global__ void zero_colsum()
{
    g_colsum[blockIdx.x * blockDim.x + threadIdx.x] = 0.f;
}

// ---------------- attention pass 2: stream S + V, exact probs -> O + column sums ----------------
#define P2_SMEM ((2*128*68 + 2*64*132 + 256) * 4)
__global__ __launch_bounds__(256, 1) void attn_pass2_t()
{
    extern __shared__ float sm[];
    float* Ss = sm;                  // 2 x [128][68]
    float* Vs = Ss + 2*128*68;       // 2 x [64][132]
    float* Cs = Vs + 2*64*132;       // [4][64]
    const int qb   = gridDim.x - 1 - blockIdx.x;
    const int h    = blockIdx.y;
    const int kv   = h >> 3;
    const int row0 = qb * 128;
    const int tid  = threadIdx.x;
    const int warp = tid >> 5;
    const int wm = warp >> 1;        // 0..3
    const int wn = warp & 1;         // 0..1
    const float scale = 0.08838834764831845f;
    const int nj = 2 * qb + 2;
    const int ncols = (qb + 1) * 128;
    const size_t sbase = (size_t)h * STOT + (size_t)16384 * ((size_t)qb * (qb + 1) / 2);

    const int rrow = tid >> 1;
    const int half = tid & 1;
    const int qi   = row0 + rrow;
    const float mr = g_m[h*SQ + qi];
    const float il = 1.0f / g_l[h*SQ + qi];

    wmma::fragment<wmma::accumulator, 16, 16, 8, float> acc_o[2][4];
#pragma unroll
    for (int i = 0; i < 2; i++)
#pragma unroll
        for (int j = 0; j < 4; j++) wmma::fill_fragment(acc_o[i][j], 0.0f);

    // tile loader: S (128x64 from packed gmem) + V (64x128), one commit group
    auto load_tiles = [&](int jb) {
        float* Sd = Ss + (jb&1) * 128*68;
        float* Vd = Vs + (jb&1) * 64*132;
        const float* Sg = g_s + sbase + (size_t)jb * 64;
#pragma unroll
        for (int it = 0; it < 8; it++) {
            int fid = tid + it * 256;
            int r = fid >> 4, c = (fid & 15) * 4;
            cp16(&Sd[r*68 + c], &Sg[(size_t)r * ncols + c]);
        }
#pragma unroll
        for (int it = 0; it < 8; it++) {
            int fid = tid + it * 256;
            int r = fid >> 5, c = (fid & 31) * 4;
            cp16(&Vd[r*132 + c], &g_v[(size_t)(jb*64 + r) * (NKV_*HD_) + kv*HD_ + c]);
        }
        CP_COMMIT();
    };

    load_tiles(0);

    for (int jb = 0; jb < nj; jb++) {
        const int col0 = jb * 64;
        if (jb + 1 < nj) { load_tiles(jb + 1); CP_WAIT(1); }
        else             { CP_WAIT(0); }
        __syncthreads();
        float* Sb = Ss + (jb&1) * 128*68;
        const float* Vb = Vs + (jb&1) * 64*132;

        // exact normalized probs in place (tf32-rounded for PV)
        {
            float* srow = &Sb[rrow*68 + half*32];
            const int cb = col0 + half*32;
#pragma unroll
            for (int c = 0; c < 32; c++) {
                float s = (cb + c <= qi) ? srow[c]*scale : -1e30f;
                srow[c] = t32(__expf(s - mr) * il);
            }
        }
        __syncthreads();

        // column-sum partials
        {
            int col = tid & 63, seg = tid >> 6;
            float cs = 0.f;
#pragma unroll 8
            for (int r = 0; r < 32; r++)
                cs += Sb[(seg*32 + r)*68 + col];
            Cs[seg*64 + col] = cs;
        }
        __syncthreads();
        if (tid < 64)
            atomicAdd(&g_colsum[h*SQ + col0 + tid],
                      Cs[tid] + Cs[64+tid] + Cs[128+tid] + Cs[192+tid]);

        // O += P @ V
#pragma unroll
        for (int k0 = 0; k0 < 64; k0 += 8) {
            wmma::fragment<wmma::matrix_a, 16, 16, 8, wmma::precision::tf32, wmma::row_major> pf[2];
            wmma::fragment<wmma::matrix_b, 16, 16, 8, wmma::precision::tf32, wmma::row_major> vf[4];
#pragma unroll
            for (int i = 0; i < 2; i++)
                wmma::load_matrix_sync(pf[i], &Sb[(wm*32 + i*16)*68 + k0], 68);
#pragma unroll
            for (int j = 0; j < 4; j++)
                wmma::load_matrix_sync(vf[j], &Vb[k0*132 + wn*64 + j*16], 132);
#pragma unroll
            for (int i = 0; i < 2; i++)
#pragma unroll
                for (int j = 0; j < 4; j++)
                    wmma::mma_sync(acc_o[i][j], pf[i], vf[j], acc_o[i][j]);
        }
        __syncthreads();   // before buffers of this parity are overwritten
    }

    // round O (tensor input of O-proj), then store
#pragma unroll
    for (int i = 0; i < 2; i++)
#pragma unroll
        for (int j = 0; j < 4; j++) {
#pragma unroll
            for (int e = 0; e < acc_o[i][j].num_elements; e++)
                acc_o[i][j].x[e] = t32(acc_o[i][j].x[e]);
            wmma::store_matrix_sync(
                &g_attn[(size_t)(row0 + wm*32 + i*16) * (NH_*HD_) + h*HD_ + wn*64 + j*16],
                acc_o[i][j], NH_*HD_, wmma::mem_row_major);
        }
}

// ---------------- finalize accumulated_scores ----------------
__global__ void finalize_acc(float* __restrict__ out_acc)
{
    int idx = blockIdx.x * blockDim.x + threadIdx.x;  // 0..8191
    int kvh = idx >> 12;
    int col = idx & 4095;
    float s = 0.f;
#pragma unroll
    for (int g = 0; g < GRP_; g++)
        s += g_colsum[(kvh*GRP_ + g)*SQ + col];
    out_acc[idx] = s * 0.125f;
}

// ---------------- launch ----------------
extern "C" void kernel_launch(void* const* d_in, const int* in_sizes, int n_in,
                              void* d_out, int out_size)
{
    const float* hs = (const float*)d_in[0];
    const float* qw = (const float*)d_in[1];
    const float* qbias = (const float*)d_in[2];
    const float* kw = (const float*)d_in[3];
    const float* kbias = (const float*)d_in[4];
    const float* vw = (const float*)d_in[5];
    const float* vbias = (const float*)d_in[6];
    const float* ow = (const float*)d_in[7];
    float* out = (float*)d_out;

    float *qp, *kp, *vp;
    float *hst, *qwt, *kwt, *vwt, *owt;
    cudaGetSymbolAddress((void**)&qp, g_q);
    cudaGetSymbolAddress((void**)&kp, g_k);
    cudaGetSymbolAddress((void**)&vp, g_v);
    cudaGetSymbolAddress((void**)&hst, g_hst);
    cudaGetSymbolAddress((void**)&qwt, g_qwt);
    cudaGetSymbolAddress((void**)&kwt, g_kwt);
    cudaGetSymbolAddress((void**)&vwt, g_vwt);
    cudaGetSymbolAddress((void**)&owt, g_owt);

    cudaFuncSetAttribute(gemm_qkv, cudaFuncAttributeMaxDynamicSharedMemorySize, GEMM_SMEM_BYTES);
    cudaFuncSetAttribute(gemm_o,   cudaFuncAttributeMaxDynamicSharedMemorySize, GEMM_SMEM_BYTES);
    cudaFuncSetAttribute(attn_pass1_t, cudaFuncAttributeMaxDynamicSharedMemorySize, P1_SMEM);
    cudaFuncSetAttribute(attn_pass2_t, cudaFuncAttributeMaxDynamicSharedMemorySize, P2_SMEM);

    compute_invfreq<<<1, 64>>>();

    // pre-round all tensor operands once
    copy_round4<<<(SQ*HID_/4 + 255)/256, 256>>>(hst, hs, SQ*HID_/4);
    copy_round4<<<(NH_*HD_*HID_/4 + 255)/256, 256>>>(qwt, qw, NH_*HD_*HID_/4);
    copy_round4<<<(NKV_*HD_*HID_/4 + 255)/256, 256>>>(kwt, kw, NKV_*HD_*HID_/4);
    copy_round4<<<(NKV_*HD_*HID_/4 + 255)/256, 256>>>(vwt, vw, NKV_*HD_*HID_/4);
    copy_round4<<<(HID_*NH_*HD_/4 + 255)/256, 256>>>(owt, ow, HID_*NH_*HD_/4);

    // fused QKV projection
    gemm_qkv<<<dim3(20, 32), 256, GEMM_SMEM_BYTES>>>();

    rope_bias_kernel<<<(SQ*NH_*64)/256,  256>>>(qp, qbias, NH_,  SQ*NH_*64);
    rope_bias_kernel<<<(SQ*NKV_*64)/256, 256>>>(kp, kbias, NKV_, SQ*NKV_*64);
    bias_v_kernel<<<(SQ*NKV_*HD_)/256, 256>>>(vp, vbias);

    attn_pass1_t<<<dim3(32, 16), 256, P1_SMEM>>>();
    zero_colsum<<<(NH_*SQ)/256, 256>>>();
    attn_pass2_t<<<dim3(32, 16), 256, P2_SMEM>>>();

    gemm_o<<<dim3(16, 32), 256, GEMM_SMEM_BYTES>>>(out);
    finalize_acc<<<(NKV_*SQ)/256, 256>>>(out + (out_size - NKV_*SQ));
}

// round 14
// speedup vs baseline: 2.4287x; 1.0130x over previous
#include <cuda_runtime.h>
#include <mma.h>
#include <math.h>
#include <stdint.h>

using namespace nvcuda;

#define SQ    4096
#define NH_   16
#define NKV_  2
#define HD_   128
#define HID_  2048
#define GRP_  8
// per-head causal-packed S scratch: sum_qb 128*(qb+1)*128 = 16384*528
#define STOT  8650752

// ---------------- scratch (device globals; no allocation allowed) ----------------
__device__ float g_q[SQ * NH_ * HD_];      // [s][h*128+d]   (tf32-rounded after rope)
__device__ float g_k[SQ * NKV_ * HD_];
__device__ float g_v[SQ * NKV_ * HD_];
__device__ float g_attn[SQ * NH_ * HD_];   // tf32-rounded at store
__device__ float g_m[NH_ * SQ];
__device__ float g_l[NH_ * SQ];
__device__ float g_colsum[NH_ * SQ];
__device__ float g_invfreq[64];
// tf32-pre-rounded operand copies
__device__ float g_hst[SQ * HID_];
__device__ float g_qwt[NH_ * HD_ * HID_];
__device__ float g_kwt[NKV_ * HD_ * HID_];
__device__ float g_vwt[NKV_ * HD_ * HID_];
__device__ float g_owt[HID_ * NH_ * HD_];
// materialized raw attention logits (pre-scale), causal-packed
__device__ float g_s[(size_t)NH_ * STOT];

__device__ __forceinline__ float t32(float x) { return wmma::__float_to_tf32(x); }

__device__ __forceinline__ void cp16(void* smem, const void* gmem)
{
    unsigned s = (unsigned)__cvta_generic_to_shared(smem);
    asm volatile("cp.async.cg.shared.global [%0], [%1], 16;\n" :: "r"(s), "l"(gmem));
}
#define CP_COMMIT()  asm volatile("cp.async.commit_group;\n")
#define CP_WAIT(n)   asm volatile("cp.async.wait_group %0;\n" :: "n"(n))

// ---------------- exact inv_freq table ----------------
__global__ void compute_invfreq()
{
    int j = threadIdx.x;
    if (j < 64) g_invfreq[j] = (float)(1.0 / pow(1.0e6, (double)j / 64.0));
}

// ---------------- pre-round to tf32 (vectorized) ----------------
__global__ void copy_round4(float* __restrict__ dst, const float* __restrict__ src, int n4)
{
    int i = blockIdx.x * blockDim.x + threadIdx.x;
    if (i >= n4) return;
    float4 v = ((const float4*)src)[i];
    v.x = t32(v.x); v.y = t32(v.y); v.z = t32(v.z); v.w = t32(v.w);
    ((float4*)dst)[i] = v;
}

// ---------------- pipelined TF32 NT GEMM core v2 ----------------
// BM=128, BN=256, BK=32, 3-stage cp.async, 256 threads, warp tile 64x64
#define GEMM_SMEM_BYTES (3 * 384 * 36 * 4)   // 165888
__device__ __forceinline__ void gemm_core(const float* __restrict__ Ag,
                                          const float* __restrict__ Bg,
                                          float* __restrict__ Cg,
                                          int K, int ldc)
{
    extern __shared__ float sm[];
    const int tid  = threadIdx.x;
    const int warp = tid >> 5;
    const int wm = warp >> 2;        // 0..1 -> 64 rows
    const int wn = warp & 3;         // 0..3 -> 64 cols

    wmma::fragment<wmma::accumulator, 16, 16, 8, float> acc[4][4];
#pragma unroll
    for (int i = 0; i < 4; i++)
#pragma unroll
        for (int j = 0; j < 4; j++) wmma::fill_fragment(acc[i][j], 0.0f);

    const int nk = K >> 5;

    auto cp_stage = [&](int t) {
        float* base = sm + (t % 3) * (384 * 36);
        const float* As = Ag + t * 32;
        const float* Bs = Bg + t * 32;
#pragma unroll
        for (int it = 0; it < 4; it++) {
            int fid = tid + it * 256;
            int r = fid >> 3, c = (fid & 7) * 4;
            cp16(&base[r*36 + c], &As[(size_t)r * K + c]);
        }
#pragma unroll
        for (int it = 0; it < 8; it++) {
            int fid = tid + it * 256;
            int r = fid >> 3, c = (fid & 7) * 4;
            cp16(&base[128*36 + r*36 + c], &Bs[(size_t)r * K + c]);
        }
        CP_COMMIT();
    };

    cp_stage(0);
    cp_stage(1);

    for (int t = 0; t < nk; t++) {
        if (t + 2 < nk) cp_stage(t + 2);
        else            CP_COMMIT();
        CP_WAIT(2);
        __syncthreads();
        const float* Ab = sm + (t % 3) * (384 * 36);
        const float* Bb = Ab + 128 * 36;
#pragma unroll
        for (int kk = 0; kk < 4; kk++) {
            wmma::fragment<wmma::matrix_a, 16, 16, 8, wmma::precision::tf32, wmma::row_major> af[4];
            wmma::fragment<wmma::matrix_b, 16, 16, 8, wmma::precision::tf32, wmma::col_major> bf[4];
#pragma unroll
            for (int i = 0; i < 4; i++)
                wmma::load_matrix_sync(af[i], &Ab[(wm*64 + i*16)*36 + kk*8], 36);
#pragma unroll
            for (int j = 0; j < 4; j++)
                wmma::load_matrix_sync(bf[j], &Bb[(wn*64 + j*16)*36 + kk*8], 36);
#pragma unroll
            for (int i = 0; i < 4; i++)
#pragma unroll
                for (int j = 0; j < 4; j++)
                    wmma::mma_sync(acc[i][j], af[i], bf[j], acc[i][j]);
        }
        __syncthreads();
    }
#pragma unroll
    for (int i = 0; i < 4; i++)
#pragma unroll
        for (int j = 0; j < 4; j++)
            wmma::store_matrix_sync(&Cg[(size_t)(wm*64 + i*16) * ldc + wn*64 + j*16],
                                    acc[i][j], ldc, wmma::mem_row_major);
}

// fused QKV projection: grid (10, 32). nt 0..7 -> Q, 8 -> K, 9 -> V
__global__ __launch_bounds__(256, 1) void gemm_qkv()
{
    const int nt = blockIdx.x, mt = blockIdx.y;
    const float* B; float* Cb; int ldc;
    if (nt < 8)       { B = g_qwt + (size_t)nt*256*HID_; Cb = g_q + (size_t)mt*128*(NH_*HD_) + nt*256; ldc = NH_*HD_; }
    else if (nt == 8) { B = g_kwt;                       Cb = g_k + (size_t)mt*128*(NKV_*HD_);         ldc = NKV_*HD_; }
    else              { B = g_vwt;                       Cb = g_v + (size_t)mt*128*(NKV_*HD_);         ldc = NKV_*HD_; }
    gemm_core(g_hst + (size_t)mt*128*HID_, B, Cb, HID_, ldc);
}

// output projection: grid (8, 32)
__global__ __launch_bounds__(256, 1) void gemm_o(float* __restrict__ out)
{
    const int nt = blockIdx.x, mt = blockIdx.y;
    gemm_core(g_attn + (size_t)mt*128*(NH_*HD_),
              g_owt  + (size_t)nt*256*(NH_*HD_),
              out    + (size_t)mt*128*HID_ + nt*256,
              NH_*HD_, HID_);
}

// ---------------- RoPE in-place with fused bias add; rounds output to tf32 ----------------
__global__ void rope_bias_kernel(float* __restrict__ x, const float* __restrict__ bias,
                                 int nheads, int total)
{
    int idx = blockIdx.x * blockDim.x + threadIdx.x;
    if (idx >= total) return;
    int j = idx & 63;
    int h = (idx >> 6) % nheads;
    int s = (idx >> 6) / nheads;
    float fr = (float)s * g_invfreq[j];
    float c, sn;
    sincosf(fr, &sn, &c);
    float* p = x + (size_t)s * nheads * HD_ + h * HD_;
    float x1 = p[j]      + bias[h*HD_ + j];
    float x2 = p[j + 64] + bias[h*HD_ + j + 64];
    p[j]      = t32(x1 * c - x2 * sn);
    p[j + 64] = t32(x2 * c + x1 * sn);
}

// ---------------- V bias add (rounds output) ----------------
__global__ void bias_v_kernel(float* __restrict__ v, const float* __restrict__ b)
{
    int i = blockIdx.x * blockDim.x + threadIdx.x;
    v[i] = t32(v[i] + b[i & (NKV_*HD_ - 1)]);
}

// ---------------- attention pass 1 v2: Q frags register-cached, 128-col K tiles ----------------
#define P1_SMEM (3 * 128 * 132 * 4)   // Ss + 2-stage K ring = 202752
__global__ __launch_bounds__(256, 1) void attn_pass1_t()
{
    extern __shared__ float sm[];
    float* Ss = sm;                  // [128][132] : Q staging, then S tile
    float* Ks = sm + 128*132;        // 2 x [128][132]
    const int qb   = gridDim.x - 1 - blockIdx.x;
    const int h    = blockIdx.y;
    const int kv   = h >> 3;
    const int row0 = qb * 128;
    const int tid  = threadIdx.x;
    const int warp = tid >> 5;
    const int wm = warp >> 1;        // 0..3 -> 32 rows
    const int wn = warp & 1;         // 0..1 -> 64 cols
    const float scale = 0.08838834764831845f;
    const int ncols = (qb + 1) * 128;
    const size_t sbase = (size_t)h * STOT + (size_t)16384 * ((size_t)qb * (qb + 1) / 2);
    const int nj = qb + 1;

    // preload K tile 0 (128 seq rows x 128 d)
#pragma unroll
    for (int it = 0; it < 16; it++) {
        int fid = tid + it * 256;
        int r = fid >> 5, c = (fid & 31) * 4;
        cp16(&Ks[r*132 + c], &g_k[(size_t)r * (NKV_*HD_) + kv*HD_ + c]);
    }
    CP_COMMIT();

    // stage Q into Ss, cache all a-fragments in registers
#pragma unroll
    for (int it = 0; it < 16; it++) {
        int fid = tid + it * 256;
        int r = fid >> 5, c = (fid & 31) * 4;
        *(float4*)&Ss[r*132 + c] =
            *(const float4*)&g_q[(size_t)(row0 + r) * (NH_*HD_) + h*HD_ + c];
    }
    __syncthreads();
    wmma::fragment<wmma::matrix_a, 16, 16, 8, wmma::precision::tf32, wmma::row_major> afc[2][16];
#pragma unroll
    for (int i = 0; i < 2; i++)
#pragma unroll
        for (int d = 0; d < 16; d++)
            wmma::load_matrix_sync(afc[i][d], &Ss[(wm*32 + i*16)*132 + d*8], 132);

    const int rrow = tid >> 1;
    const int half = tid & 1;
    const int qi   = row0 + rrow;
    float m_run = -1e30f, l_run = 0.f;

    for (int jb = 0; jb < nj; jb++) {
        if (jb + 1 < nj) {
            float* dst = Ks + ((jb+1)&1) * 128*132;
            const int r0n = (jb+1) * 128;
#pragma unroll
            for (int it = 0; it < 16; it++) {
                int fid = tid + it * 256;
                int r = fid >> 5, c = (fid & 31) * 4;
                cp16(&dst[r*132 + c], &g_k[(size_t)(r0n + r) * (NKV_*HD_) + kv*HD_ + c]);
            }
            CP_COMMIT();
            CP_WAIT(1);
        } else {
            CP_WAIT(0);
        }
        __syncthreads();   // K visible; afc loads + prev-iter Ss readers all done
        const float* Kb = Ks + (jb&1) * 128*132;

        wmma::fragment<wmma::accumulator, 16, 16, 8, float> acc[2][4];
#pragma unroll
        for (int i = 0; i < 2; i++)
#pragma unroll
            for (int j = 0; j < 4; j++) wmma::fill_fragment(acc[i][j], 0.0f);
#pragma unroll
        for (int d = 0; d < 16; d++) {
            wmma::fragment<wmma::matrix_b, 16, 16, 8, wmma::precision::tf32, wmma::col_major> bf[4];
#pragma unroll
            for (int j = 0; j < 4; j++)
                wmma::load_matrix_sync(bf[j], &Kb[(wn*64 + j*16)*132 + d*8], 132);
#pragma unroll
            for (int i = 0; i < 2; i++)
#pragma unroll
                for (int j = 0; j < 4; j++)
                    wmma::mma_sync(acc[i][j], afc[i][d], bf[j], acc[i][j]);
        }
#pragma unroll
        for (int i = 0; i < 2; i++)
#pragma unroll
            for (int j = 0; j < 4; j++)
                wmma::store_matrix_sync(&Ss[(wm*32 + i*16)*132 + wn*64 + j*16],
                                        acc[i][j], 132, wmma::mem_row_major);
        __syncthreads();

        // online (m, l) stats over 128 cols; row owned by thread pair
        {
            const float* srow = &Ss[rrow*132 + half*64];
            const int cb = jb*128 + half*64;
            float lmax = -1e30f;
#pragma unroll
            for (int c = 0; c < 64; c++) {
                float s = (cb + c <= qi) ? srow[c]*scale : -1e30f;
                lmax = fmaxf(lmax, s);
            }
            lmax = fmaxf(lmax, __shfl_xor_sync(0xffffffffu, lmax, 1));
            float nm = fmaxf(m_run, lmax);
            float ps = 0.f;
#pragma unroll
            for (int c = 0; c < 64; c++) {
                float s = (cb + c <= qi) ? srow[c]*scale : -1e30f;
                ps += __expf(s - nm);
            }
            ps += __shfl_xor_sync(0xffffffffu, ps, 1);
            l_run = l_run * __expf(m_run - nm) + ps;
            m_run = nm;
        }

        // write raw S tile (128 x 128) to gmem for pass2
        {
            float* dst = g_s + sbase + (size_t)jb * 128;
#pragma unroll
            for (int it = 0; it < 16; it++) {
                int fid = tid + it * 256;
                int r = fid >> 5, c = (fid & 31) * 4;
                *(float4*)&dst[(size_t)r * ncols + c] = *(const float4*)&Ss[r*132 + c];
            }
        }
        __syncthreads();
    }
    if (half == 0) {
        g_m[h*SQ + qi] = m_run;
        g_l[h*SQ + qi] = l_run;
    }
}

// ---------------- zero colsum ----------------
__global__ void zero_colsum()
{
    g_colsum[blockIdx.x * blockDim.x + threadIdx.x] = 0.f;
}

// ---------------- attention pass 2: stream S + V, exact probs -> O + column sums ----------------
#define P2_SMEM ((2*128*68 + 2*64*132 + 256) * 4)
__global__ __launch_bounds__(256, 1) void attn_pass2_t()
{
    extern __shared__ float sm[];
    float* Ss = sm;                  // 2 x [128][68]
    float* Vs = Ss + 2*128*68;       // 2 x [64][132]
    float* Cs = Vs + 2*64*132;       // [4][64]
    const int qb   = gridDim.x - 1 - blockIdx.x;
    const int h    = blockIdx.y;
    const int kv   = h >> 3;
    const int row0 = qb * 128;
    const int tid  = threadIdx.x;
    const int warp = tid >> 5;
    const int wm = warp >> 1;        // 0..3
    const int wn = warp & 1;         // 0..1
    const float scale = 0.08838834764831845f;
    const int nj = 2 * qb + 2;
    const int ncols = (qb + 1) * 128;
    const size_t sbase = (size_t)h * STOT + (size_t)16384 * ((size_t)qb * (qb + 1) / 2);

    const int rrow = tid >> 1;
    const int half = tid & 1;
    const int qi   = row0 + rrow;
    const float mr = g_m[h*SQ + qi];
    const float il = 1.0f / g_l[h*SQ + qi];

    wmma::fragment<wmma::accumulator, 16, 16, 8, float> acc_o[2][4];
#pragma unroll
    for (int i = 0; i < 2; i++)
#pragma unroll
        for (int j = 0; j < 4; j++) wmma::fill_fragment(acc_o[i][j], 0.0f);

    // tile loader: S (128x64 from packed gmem) + V (64x128), one commit group
    auto load_tiles = [&](int jb) {
        float* Sd = Ss + (jb&1) * 128*68;
        float* Vd = Vs + (jb&1) * 64*132;
        const float* Sg = g_s + sbase + (size_t)jb * 64;
#pragma unroll
        for (int it = 0; it < 8; it++) {
            int fid = tid + it * 256;
            int r = fid >> 4, c = (fid & 15) * 4;
            cp16(&Sd[r*68 + c], &Sg[(size_t)r * ncols + c]);
        }
#pragma unroll
        for (int it = 0; it < 8; it++) {
            int fid = tid + it * 256;
            int r = fid >> 5, c = (fid & 31) * 4;
            cp16(&Vd[r*132 + c], &g_v[(size_t)(jb*64 + r) * (NKV_*HD_) + kv*HD_ + c]);
        }
        CP_COMMIT();
    };

    load_tiles(0);

    for (int jb = 0; jb < nj; jb++) {
        const int col0 = jb * 64;
        if (jb + 1 < nj) { load_tiles(jb + 1); CP_WAIT(1); }
        else             { CP_WAIT(0); }
        __syncthreads();
        float* Sb = Ss + (jb&1) * 128*68;
        const float* Vb = Vs + (jb&1) * 64*132;

        // exact normalized probs in place (tf32-rounded for PV)
        {
            float* srow = &Sb[rrow*68 + half*32];
            const int cb = col0 + half*32;
#pragma unroll
            for (int c = 0; c < 32; c++) {
                float s = (cb + c <= qi) ? srow[c]*scale : -1e30f;
                srow[c] = t32(__expf(s - mr) * il);
            }
        }
        __syncthreads();

        // column-sum partials
        {
            int col = tid & 63, seg = tid >> 6;
            float cs = 0.f;
#pragma unroll 8
            for (int r = 0; r < 32; r++)
                cs += Sb[(seg*32 + r)*68 + col];
            Cs[seg*64 + col] = cs;
        }
        __syncthreads();
        if (tid < 64)
            atomicAdd(&g_colsum[h*SQ + col0 + tid],
                      Cs[tid] + Cs[64+tid] + Cs[128+tid] + Cs[192+tid]);

        // O += P @ V
#pragma unroll
        for (int k0 = 0; k0 < 64; k0 += 8) {
            wmma::fragment<wmma::matrix_a, 16, 16, 8, wmma::precision::tf32, wmma::row_major> pf[2];
            wmma::fragment<wmma::matrix_b, 16, 16, 8, wmma::precision::tf32, wmma::row_major> vf[4];
#pragma unroll
            for (int i = 0; i < 2; i++)
                wmma::load_matrix_sync(pf[i], &Sb[(wm*32 + i*16)*68 + k0], 68);
#pragma unroll
            for (int j = 0; j < 4; j++)
                wmma::load_matrix_sync(vf[j], &Vb[k0*132 + wn*64 + j*16], 132);
#pragma unroll
            for (int i = 0; i < 2; i++)
#pragma unroll
                for (int j = 0; j < 4; j++)
                    wmma::mma_sync(acc_o[i][j], pf[i], vf[j], acc_o[i][j]);
        }
        __syncthreads();   // before buffers of this parity are overwritten
    }

    // round O (tensor input of O-proj), then store
#pragma unroll
    for (int i = 0; i < 2; i++)
#pragma unroll
        for (int j = 0; j < 4; j++) {
#pragma unroll
            for (int e = 0; e < acc_o[i][j].num_elements; e++)
                acc_o[i][j].x[e] = t32(acc_o[i][j].x[e]);
            wmma::store_matrix_sync(
                &g_attn[(size_t)(row0 + wm*32 + i*16) * (NH_*HD_) + h*HD_ + wn*64 + j*16],
                acc_o[i][j], NH_*HD_, wmma::mem_row_major);
        }
}

// ---------------- finalize accumulated_scores ----------------
__global__ void finalize_acc(float* __restrict__ out_acc)
{
    int idx = blockIdx.x * blockDim.x + threadIdx.x;  // 0..8191
    int kvh = idx >> 12;
    int col = idx & 4095;
    float s = 0.f;
#pragma unroll
    for (int g = 0; g < GRP_; g++)
        s += g_colsum[(kvh*GRP_ + g)*SQ + col];
    out_acc[idx] = s * 0.125f;
}

// ---------------- launch ----------------
extern "C" void kernel_launch(void* const* d_in, const int* in_sizes, int n_in,
                              void* d_out, int out_size)
{
    const float* hs = (const float*)d_in[0];
    const float* qw = (const float*)d_in[1];
    const float* qbias = (const float*)d_in[2];
    const float* kw = (const float*)d_in[3];
    const float* kbias = (const float*)d_in[4];
    const float* vw = (const float*)d_in[5];
    const float* vbias = (const float*)d_in[6];
    const float* ow = (const float*)d_in[7];
    float* out = (float*)d_out;

    float *qp, *kp, *vp;
    float *hst, *qwt, *kwt, *vwt, *owt;
    cudaGetSymbolAddress((void**)&qp, g_q);
    cudaGetSymbolAddress((void**)&kp, g_k);
    cudaGetSymbolAddress((void**)&vp, g_v);
    cudaGetSymbolAddress((void**)&hst, g_hst);
    cudaGetSymbolAddress((void**)&qwt, g_qwt);
    cudaGetSymbolAddress((void**)&kwt, g_kwt);
    cudaGetSymbolAddress((void**)&vwt, g_vwt);
    cudaGetSymbolAddress((void**)&owt, g_owt);

    cudaFuncSetAttribute(gemm_qkv, cudaFuncAttributeMaxDynamicSharedMemorySize, GEMM_SMEM_BYTES);
    cudaFuncSetAttribute(gemm_o,   cudaFuncAttributeMaxDynamicSharedMemorySize, GEMM_SMEM_BYTES);
    cudaFuncSetAttribute(attn_pass1_t, cudaFuncAttributeMaxDynamicSharedMemorySize, P1_SMEM);
    cudaFuncSetAttribute(attn_pass2_t, cudaFuncAttributeMaxDynamicSharedMemorySize, P2_SMEM);

    compute_invfreq<<<1, 64>>>();

    // pre-round all tensor operands once
    copy_round4<<<(SQ*HID_/4 + 255)/256, 256>>>(hst, hs, SQ*HID_/4);
    copy_round4<<<(NH_*HD_*HID_/4 + 255)/256, 256>>>(qwt, qw, NH_*HD_*HID_/4);
    copy_round4<<<(NKV_*HD_*HID_/4 + 255)/256, 256>>>(kwt, kw, NKV_*HD_*HID_/4);
    copy_round4<<<(NKV_*HD_*HID_/4 + 255)/256, 256>>>(vwt, vw, NKV_*HD_*HID_/4);
    copy_round4<<<(HID_*NH_*HD_/4 + 255)/256, 256>>>(owt, ow, HID_*NH_*HD_/4);

    // fused QKV projection
    gemm_qkv<<<dim3(10, 32), 256, GEMM_SMEM_BYTES>>>();

    rope_bias_kernel<<<(SQ*NH_*64)/256,  256>>>(qp, qbias, NH_,  SQ*NH_*64);
    rope_bias_kernel<<<(SQ*NKV_*64)/256, 256>>>(kp, kbias, NKV_, SQ*NKV_*64);
    bias_v_kernel<<<(SQ*NKV_*HD_)/256, 256>>>(vp, vbias);

    attn_pass1_t<<<dim3(32, 16), 256, P1_SMEM>>>();
    zero_colsum<<<(NH_*SQ)/256, 256>>>();
    attn_pass2_t<<<dim3(32, 16), 256, P2_SMEM>>>();

    gemm_o<<<dim3(8, 32), 256, GEMM_SMEM_BYTES>>>(out);
    finalize_acc<<<(NKV_*SQ)/256, 256>>>(out + (out_size - NKV_*SQ));
}